// round 7
// baseline (speedup 1.0000x reference)
#include <cuda_runtime.h>
#include <cuda_fp16.h>
#include <math.h>
#include <stdint.h>

#define LOG2E_F 1.4426950408889634f

// ---------------- scratch (static device globals; no allocs) ----------------
__device__ float g_f[32 * 1024 * 128];       // f = fi@Wf + bf           16 MB
__device__ float g_K[32 * 64 * 1024];        // M' -> K~ (in place)       8 MB
__device__ float g_r[32 * 65];               // Sinkhorn row scalings
__device__ float g_c[32 * 1024];             // Sinkhorn col scalings
__device__ float g_vpart[32 * 8 * 64 * 128]; // split-K partials of p@f
__device__ float g_pspart[32 * 8 * 64];      // split-K partials of rowsum(p)
__device__ float g_t[32 * 256];              // t = x0 @ Wt + bt
__device__ __half g_Bhi[192 * 768];          // (W^T * 256) hi, [n][k]
__device__ __half g_Blo[192 * 768];          // (W^T * 256) lo

// ------------------------------- helpers -------------------------------------
__device__ __forceinline__ float warpSum(float v) {
    #pragma unroll
    for (int o = 16; o > 0; o >>= 1) v += __shfl_xor_sync(0xffffffffu, v, o);
    return v;
}
__device__ __forceinline__ float warpMax(float v) {
    #pragma unroll
    for (int o = 16; o > 0; o >>= 1) v = fmaxf(v, __shfl_xor_sync(0xffffffffu, v, o));
    return v;
}
// exp2 on the FMA pipe (x <= 0 here). deg-5 Taylor on [-0.5,0.5], rel err ~2e-6.
__device__ __forceinline__ float exp2_fma(float x) {
    x = fmaxf(x, -125.0f);
    int   ni = __float2int_rn(x);
    float f  = x - (float)ni;
    float p  = 1.3333558e-3f;
    p = fmaf(p, f, 9.6181290e-3f);
    p = fmaf(p, f, 5.5504109e-2f);
    p = fmaf(p, f, 2.4022651e-1f);
    p = fmaf(p, f, 6.9314718e-1f);
    p = fmaf(p, f, 1.0f);
    return p * __int_as_float((ni + 127) << 23);
}
__device__ __forceinline__ void mma16816(float* d, uint32_t a0, uint32_t a1,
                                         uint32_t a2, uint32_t a3,
                                         uint32_t b0, uint32_t b1) {
    asm volatile(
        "mma.sync.aligned.m16n8k16.row.col.f32.f16.f16.f32 "
        "{%0,%1,%2,%3}, {%4,%5,%6,%7}, {%8,%9}, {%0,%1,%2,%3};"
        : "+f"(d[0]), "+f"(d[1]), "+f"(d[2]), "+f"(d[3])
        : "r"(a0), "r"(a1), "r"(a2), "r"(a3), "r"(b0), "r"(b1));
}
__device__ __forceinline__ void ldsm4(uint32_t& r0, uint32_t& r1,
                                      uint32_t& r2, uint32_t& r3, uint32_t a) {
    asm volatile("ldmatrix.sync.aligned.m8n8.x4.shared.b16 {%0,%1,%2,%3}, [%4];"
                 : "=r"(r0), "=r"(r1), "=r"(r2), "=r"(r3) : "r"(a));
}
__device__ __forceinline__ uint32_t pack_h2(__half a, __half b) {
    __half2 h = __halves2half2(a, b);
    return *(uint32_t*)&h;
}
__device__ __forceinline__ uint32_t smem_u32(const void* p) {
    uint32_t a;
    asm("{ .reg .u64 t; cvta.to.shared.u64 t, %1; cvt.u32.u64 %0, t; }" : "=r"(a) : "l"(p));
    return a;
}
__device__ __forceinline__ void cpasync16(uint32_t dst, const void* src) {
    asm volatile("cp.async.cg.shared.global [%0], [%1], 16;" :: "r"(dst), "l"(src));
}
#define CP_COMMIT() asm volatile("cp.async.commit_group;" ::: "memory")
#define CP_WAIT0()  asm volatile("cp.async.wait_group 0;" ::: "memory")
#define CP_WAIT1()  asm volatile("cp.async.wait_group 1;" ::: "memory")

// ------------------- prepB (split in two for launch-slot layout) -------------
__global__ __launch_bounds__(256) void prepBf(const float* __restrict__ Wf)
{
    int i = blockIdx.x * 256 + threadIdx.x;     // 128*768
    int n = i / 768, k = i - n * 768;
    float v = Wf[(size_t)k * 128 + n] * 256.0f;
    __half hi = __float2half_rn(v);
    g_Bhi[i] = hi;
    g_Blo[i] = __float2half_rn(v - __half2float(hi));
}
__global__ __launch_bounds__(256) void prepBs(const float* __restrict__ Ws)
{
    int i = blockIdx.x * 256 + threadIdx.x;     // 64*768
    int n = i / 768, k = i - n * 768;
    float v = Ws[(size_t)k * 64 + n] * 256.0f;
    __half hi = __float2half_rn(v);
    g_Bhi[128 * 768 + i] = hi;
    g_Blo[128 * 768 + i] = __float2half_rn(v - __half2float(hi));
}

// --------------------------- tG: t = x[:,0] @ Wt + bt ------------------------
__global__ __launch_bounds__(256) void tG(
    const float* __restrict__ x, const float* __restrict__ Wt,
    const float* __restrict__ bt)
{
    const int b = blockIdx.x;
    const int c = threadIdx.x;
    __shared__ float xs[768];
    for (int i = c; i < 768; i += 256) xs[i] = x[(size_t)b * 1025 * 768 + i];
    __syncthreads();
    float acc = bt[c];
    #pragma unroll 8
    for (int d = 0; d < 768; d++) acc = fmaf(xs[d], Wt[(size_t)d * 256 + c], acc);
    g_t[b * 256 + c] = acc;
}

// ---------------------------------------------------------------------------
// gemmA via mma.sync + ldmatrix, software-pipelined, 512 threads (16 warps).
// Warp grid 4x4: wr = rows 32*wr, wc = cols 48*wc.
// f cols (<128): 2-term split (Ahi*Bhi + Ahi*Blo); s cols (>=128): 3-term.
// ---------------------------------------------------------------------------
#define SMA_HI 0
#define SMA_LO (128 * 144)
#define SMB(buf) (2 * 128 * 144 + (buf) * (2 * 192 * 144))
#define SMB_LO_OFF (192 * 144)
#define SMB_STRIDE (2 * 192 * 144)
#define SM_TOTAL (2 * 128 * 144 + 2 * 2 * 192 * 144)   // 147456 B

__global__ __launch_bounds__(512) void gemmA_mma(
    const float* __restrict__ x, const float* __restrict__ bf,
    const float* __restrict__ bs, const float* __restrict__ sharp)
{
    extern __shared__ char sm[];
    const uint32_t smu = smem_u32(sm);
    const int tid = threadIdx.x, wid = tid >> 5, lane = tid & 31;
    const int b = blockIdx.y, nt = blockIdx.x;
    const int wr = wid & 3, wc = wid >> 2;          // 4 x 4 warp grid
    const int g = lane >> 2, tig = lane & 3;
    const bool haveLo = (wc >= 2);

    // per-lane ldmatrix base addresses (row = lane&15, k-half = lane>>4)
    const int rl = lane & 15, kh = lane >> 4;
    const uint32_t aHiB = smu + SMA_HI + (wr * 32 + rl) * 144 + kh * 16;
    const uint32_t aLoB = aHiB + (SMA_LO - SMA_HI);
    const uint32_t bHiB0 = smu + SMB(0) + (wc * 48 + rl) * 144 + kh * 16;

    const float* A = x + (size_t)b * 1025 * 768 + 768 + (size_t)nt * 128 * 768;
    const int am = tid >> 2, akb = (tid & 3) * 16;
    const float* aptr = A + (size_t)am * 768 + akb;

    float acc[2][6][4];
    #pragma unroll
    for (int mf = 0; mf < 2; mf++)
        #pragma unroll
        for (int nf = 0; nf < 6; nf++)
            #pragma unroll
            for (int q = 0; q < 4; q++) acc[mf][nf][q] = 0.0f;

    float4 aPre[4];
    #pragma unroll
    for (int i = 0; i < 4; i++) aPre[i] = *(const float4*)(aptr + i * 4);
    #pragma unroll
    for (int j = 0; j < 3; j++) {
        int e = tid + j * 512;
        int n = e >> 3, u = e & 7;
        uint32_t doff = (uint32_t)(n * 144 + u * 16);
        cpasync16(smu + SMB(0) + doff, g_Bhi + (size_t)n * 768 + u * 8);
        cpasync16(smu + SMB(0) + SMB_LO_OFF + doff, g_Blo + (size_t)n * 768 + u * 8);
    }
    CP_COMMIT();

    #pragma unroll 1
    for (int ch = 0; ch < 12; ch++) {
        const int buf = ch & 1;
        // ---- convert prefetched A regs -> smem hi/lo ----
        #pragma unroll
        for (int i = 0; i < 4; i++) {
            float4 v = aPre[i];
            __half hx = __float2half_rn(v.x), hy = __float2half_rn(v.y);
            __half hz = __float2half_rn(v.z), hw = __float2half_rn(v.w);
            __half lx = __float2half_rn(v.x - __half2float(hx));
            __half ly = __float2half_rn(v.y - __half2float(hy));
            __half lz = __float2half_rn(v.z - __half2float(hz));
            __half lw = __float2half_rn(v.w - __half2float(hw));
            uint32_t off = am * 144 + (akb + i * 4) * 2;
            *(uint2*)(sm + SMA_HI + off) = make_uint2(pack_h2(hx, hy), pack_h2(hz, hw));
            *(uint2*)(sm + SMA_LO + off) = make_uint2(pack_h2(lx, ly), pack_h2(lz, lw));
        }
        // ---- prefetch chunk ch+1 ----
        if (ch < 11) {
            const int k1 = (ch + 1) * 64;
            #pragma unroll
            for (int i = 0; i < 4; i++) aPre[i] = *(const float4*)(aptr + k1 + i * 4);
            #pragma unroll
            for (int j = 0; j < 3; j++) {
                int e = tid + j * 512;
                int n = e >> 3, u = e & 7;
                uint32_t doff = (uint32_t)(n * 144 + u * 16);
                cpasync16(smu + SMB(buf ^ 1) + doff, g_Bhi + (size_t)n * 768 + k1 + u * 8);
                cpasync16(smu + SMB(buf ^ 1) + SMB_LO_OFF + doff, g_Blo + (size_t)n * 768 + k1 + u * 8);
            }
            CP_COMMIT();
            CP_WAIT1();
        } else {
            CP_WAIT0();
        }
        __syncthreads();

        const uint32_t bHiB = bHiB0 + buf * SMB_STRIDE;
        const uint32_t bLoB = bHiB + SMB_LO_OFF;
        #pragma unroll
        for (int ks = 0; ks < 4; ks++) {
            const uint32_t ko = ks * 32;          // 16 halfs = 32 B per ks
            uint32_t ah[2][4], al[2][4];
            ldsm4(ah[0][0], ah[0][1], ah[0][2], ah[0][3], aHiB + ko);
            ldsm4(ah[1][0], ah[1][1], ah[1][2], ah[1][3], aHiB + 16 * 144 + ko);
            if (haveLo) {
                ldsm4(al[0][0], al[0][1], al[0][2], al[0][3], aLoB + ko);
                ldsm4(al[1][0], al[1][1], al[1][2], al[1][3], aLoB + 16 * 144 + ko);
            }
            #pragma unroll
            for (int j = 0; j < 3; j++) {
                uint32_t bh0, bh1, bh2, bh3, bl0, bl1, bl2, bl3;
                ldsm4(bh0, bh1, bh2, bh3, bHiB + j * 16 * 144 + ko);
                ldsm4(bl0, bl1, bl2, bl3, bLoB + j * 16 * 144 + ko);
                const bool third = haveLo && (wc * 48 + j * 16 >= 128);
                #pragma unroll
                for (int mf = 0; mf < 2; mf++) {
                    mma16816(acc[mf][2 * j + 0], ah[mf][0], ah[mf][1], ah[mf][2], ah[mf][3], bh0, bh2);
                    mma16816(acc[mf][2 * j + 0], ah[mf][0], ah[mf][1], ah[mf][2], ah[mf][3], bl0, bl2);
                    mma16816(acc[mf][2 * j + 1], ah[mf][0], ah[mf][1], ah[mf][2], ah[mf][3], bh1, bh3);
                    mma16816(acc[mf][2 * j + 1], ah[mf][0], ah[mf][1], ah[mf][2], ah[mf][3], bl1, bl3);
                    if (third) {
                        mma16816(acc[mf][2 * j + 0], al[mf][0], al[mf][1], al[mf][2], al[mf][3], bh0, bh2);
                        mma16816(acc[mf][2 * j + 1], al[mf][0], al[mf][1], al[mf][2], al[mf][3], bh1, bh3);
                    }
                }
            }
        }
        __syncthreads();
    }

    // ---------------------------- epilogue ----------------------------------
    const float inv256 = 1.0f / 256.0f;
    const float scl = sharp[0] * 10.0f * LOG2E_F;   // sharpness/REG * log2(e)
    #pragma unroll
    for (int mf = 0; mf < 2; mf++) {
        #pragma unroll
        for (int nf = 0; nf < 6; nf++) {
            int c = wc * 48 + nf * 8 + tig * 2;
            int r0 = nt * 128 + wr * 32 + mf * 16 + g;
            int r1 = r0 + 8;
            float d0 = acc[mf][nf][0], d1 = acc[mf][nf][1];
            float d2 = acc[mf][nf][2], d3 = acc[mf][nf][3];
            if (c < 128) {
                float b0 = __ldg(bf + c), b1 = __ldg(bf + c + 1);
                *(float2*)(g_f + ((size_t)(b * 1024 + r0)) * 128 + c) =
                    make_float2(fmaf(d0, inv256, b0), fmaf(d1, inv256, b1));
                *(float2*)(g_f + ((size_t)(b * 1024 + r1)) * 128 + c) =
                    make_float2(fmaf(d2, inv256, b0), fmaf(d3, inv256, b1));
            } else {
                int k = c - 128;
                float b0 = __ldg(bs + k), b1 = __ldg(bs + k + 1);
                float* K0 = g_K + ((size_t)(b * 64 + k)) * 1024;
                float* K1 = g_K + ((size_t)(b * 64 + k + 1)) * 1024;
                K0[r0] = fmaf(d0, inv256, b0) * scl;
                K1[r0] = fmaf(d1, inv256, b1) * scl;
                K0[r1] = fmaf(d2, inv256, b0) * scl;
                K1[r1] = fmaf(d3, inv256, b1) * scl;
            }
        }
    }
}

// ------------- expprep: rowmax + exp2 + rowsum -> initial r ------------------
__global__ __launch_bounds__(256) void expprep()
{
    const int row = blockIdx.x;              // b*64 + k
    float4* p = (float4*)(g_K + ((size_t)row << 10));
    const int t = threadIdx.x;
    float4 v = p[t];
    __shared__ float red[8];
    __shared__ float s_bm;
    float mx = fmaxf(fmaxf(v.x, v.y), fmaxf(v.z, v.w));
    mx = warpMax(mx);
    if ((t & 31) == 0) red[t >> 5] = mx;
    __syncthreads();
    if (t == 0) {
        float mm = red[0];
        #pragma unroll
        for (int i = 1; i < 8; i++) mm = fmaxf(mm, red[i]);
        s_bm = mm;
    }
    __syncthreads();
    const float m = s_bm;
    v.x = exp2_fma(v.x - m); v.y = exp2_fma(v.y - m);
    v.z = exp2_fma(v.z - m); v.w = exp2_fma(v.w - m);
    p[t] = v;
    float s = (v.x + v.y) + (v.z + v.w);
    s = warpSum(s);
    if ((t & 31) == 0) red[t >> 5] = s;
    __syncthreads();
    if (t == 0) {
        float tot = 0.0f;
        #pragma unroll
        for (int i = 0; i < 8; i++) tot += red[i];
        g_r[(row >> 6) * 65 + (row & 63)] = (1.0f / 65.0f) / tot;
        if ((row & 63) == 0) g_r[(row >> 6) * 65 + 64] = (1.0f / 65.0f) / 1024.0f;
    }
}

// ------------- fused Sinkhorn: 5 c-updates + 4 r-updates, one launch ---------
__global__ __launch_bounds__(1024) void sinkhorn()
{
    const int b = blockIdx.x;
    const int t = threadIdx.x, w = t >> 5, l = t & 31;
    __shared__ float cs[1024];
    __shared__ float rs[72];
    __shared__ float red[32];
    if (t < 65) rs[t] = g_r[b * 65 + t];
    __syncthreads();
    const float* Kb = g_K + ((size_t)b << 16);

    #pragma unroll 1
    for (int it = 0; it < 5; it++) {
        const float* col = Kb + t;
        float a0 = rs[64], a1 = 0.f, a2 = 0.f, a3 = 0.f;
        float a4 = 0.f, a5 = 0.f, a6 = 0.f, a7 = 0.f;
        #pragma unroll
        for (int k = 0; k < 64; k += 8) {
            a0 = fmaf(col[(size_t)(k + 0) << 10], rs[k + 0], a0);
            a1 = fmaf(col[(size_t)(k + 1) << 10], rs[k + 1], a1);
            a2 = fmaf(col[(size_t)(k + 2) << 10], rs[k + 2], a2);
            a3 = fmaf(col[(size_t)(k + 3) << 10], rs[k + 3], a3);
            a4 = fmaf(col[(size_t)(k + 4) << 10], rs[k + 4], a4);
            a5 = fmaf(col[(size_t)(k + 5) << 10], rs[k + 5], a5);
            a6 = fmaf(col[(size_t)(k + 6) << 10], rs[k + 6], a6);
            a7 = fmaf(col[(size_t)(k + 7) << 10], rs[k + 7], a7);
        }
        float cv = (1.0f / 1024.0f) /
                   (((a0 + a1) + (a2 + a3)) + ((a4 + a5) + (a6 + a7)));
        cs[t] = cv;
        float sw = warpSum(cv);
        if (l == 0) red[w] = sw;
        __syncthreads();
        if (it < 4) {
            if (t == 0) {
                float s = 0.0f;
                #pragma unroll
                for (int i = 0; i < 32; i++) s += red[i];
                rs[64] = (1.0f / 65.0f) / s;
            }
            #pragma unroll
            for (int rr = 0; rr < 2; rr++) {
                int k = w + rr * 32;
                const float* row = Kb + ((size_t)k << 10);
                float d0 = 0.f, d1 = 0.f, d2 = 0.f, d3 = 0.f;
                float d4 = 0.f, d5 = 0.f, d6 = 0.f, d7 = 0.f;
                #pragma unroll
                for (int n0 = 0; n0 < 1024; n0 += 256) {
                    d0 = fmaf(row[n0 + l],        cs[n0 + l],        d0);
                    d1 = fmaf(row[n0 + l + 32],   cs[n0 + l + 32],   d1);
                    d2 = fmaf(row[n0 + l + 64],   cs[n0 + l + 64],   d2);
                    d3 = fmaf(row[n0 + l + 96],   cs[n0 + l + 96],   d3);
                    d4 = fmaf(row[n0 + l + 128],  cs[n0 + l + 128],  d4);
                    d5 = fmaf(row[n0 + l + 160],  cs[n0 + l + 160],  d5);
                    d6 = fmaf(row[n0 + l + 192],  cs[n0 + l + 192],  d6);
                    d7 = fmaf(row[n0 + l + 224],  cs[n0 + l + 224],  d7);
                }
                float d = warpSum((((d0 + d1) + (d2 + d3)) + ((d4 + d5) + (d6 + d7))));
                if (l == 0) rs[k] = (1.0f / 65.0f) / d;
            }
            __syncthreads();
        }
    }
    g_c[b * 1024 + t] = cs[t];
    if (t < 65) g_r[b * 65 + t] = rs[t];
}

// ---------------------------------------------------------------------------
// GEMM C: partial (64x128) = p_slice @ f_slice, p materialized as K~ * r * c.
// ---------------------------------------------------------------------------
__global__ __launch_bounds__(256) void gemmC()
{
    const int b = blockIdx.y, sp = blockIdx.x;
    const int tid = threadIdx.x;
    const int tx = tid & 15, ty = tid >> 4;
    __shared__ float ps[64][33];
    __shared__ float fs[32][128];

    const int n0 = sp * 128;
    float acc[4][8];
    #pragma unroll
    for (int i = 0; i < 4; i++)
        #pragma unroll
        for (int j = 0; j < 8; j++) acc[i][j] = 0.0f;
    float psum = 0.0f;

    for (int c0 = 0; c0 < 128; c0 += 32) {
        __syncthreads();
        #pragma unroll
        for (int j = 0; j < 2; j++) {
            int idx4 = tid + j * 256;
            int k = idx4 >> 3;
            int nn4 = (idx4 & 7) * 4;
            float4 kv = *(const float4*)(g_K + ((size_t)(b * 64 + k)) * 1024 + n0 + c0 + nn4);
            float4 cv = *(const float4*)(g_c + b * 1024 + n0 + c0 + nn4);
            float rv = __ldg(&g_r[b * 65 + k]);
            ps[k][nn4 + 0] = kv.x * cv.x * rv;
            ps[k][nn4 + 1] = kv.y * cv.y * rv;
            ps[k][nn4 + 2] = kv.z * cv.z * rv;
            ps[k][nn4 + 3] = kv.w * cv.w * rv;
        }
        #pragma unroll
        for (int j = 0; j < 4; j++) {
            int idx4 = tid + j * 256;
            int nn = idx4 >> 5;
            int c4 = (idx4 & 31) * 4;
            *(float4*)&fs[nn][c4] =
                *(const float4*)(g_f + ((size_t)(b * 1024 + n0 + c0 + nn)) * 128 + c4);
        }
        __syncthreads();

        #pragma unroll
        for (int nn = 0; nn < 32; nn++) {
            float a4[4];
            #pragma unroll
            for (int i = 0; i < 4; i++) a4[i] = ps[ty * 4 + i][nn];
            float4 b0 = *(const float4*)&fs[nn][tx * 8];
            float4 b1 = *(const float4*)&fs[nn][tx * 8 + 4];
            float b8[8] = {b0.x, b0.y, b0.z, b0.w, b1.x, b1.y, b1.z, b1.w};
            #pragma unroll
            for (int i = 0; i < 4; i++)
                #pragma unroll
                for (int j = 0; j < 8; j++)
                    acc[i][j] = fmaf(a4[i], b8[j], acc[i][j]);
        }

        if (tid < 64) {
            float s = 0.0f;
            #pragma unroll
            for (int nn = 0; nn < 32; nn++) s += ps[tid][nn];
            psum += s;
        }
    }

    #pragma unroll
    for (int i = 0; i < 4; i++) {
        float* dst = g_vpart + (((size_t)(b * 8 + sp) * 64) + ty * 4 + i) * 128 + tx * 8;
        *(float4*)(dst)     = make_float4(acc[i][0], acc[i][1], acc[i][2], acc[i][3]);
        *(float4*)(dst + 4) = make_float4(acc[i][4], acc[i][5], acc[i][6], acc[i][7]);
    }
    if (tid < 64) g_pspart[(b * 8 + sp) * 64 + tid] = psum;
}

// ----- finalK: split-K reduce + anchors + t concat + L2 normalize ------------
__global__ __launch_bounds__(1024) void finalK(
    const float* __restrict__ anchors, float* __restrict__ out)
{
    const int b = blockIdx.x, t = threadIdx.x;
    float* orow = out + (size_t)b * 8448;
    float ss = 0.0f;

    #pragma unroll
    for (int j = 0; j < 8; j++) {
        int e = t + j * 1024;
        int k = e >> 7, c = e & 127;
        float s2 = 0.0f, sps = 0.0f;
        #pragma unroll
        for (int sp = 0; sp < 8; sp++) {
            s2  += g_vpart[(((size_t)(b * 8 + sp) * 64) + k) * 128 + c];
            sps += g_pspart[(b * 8 + sp) * 64 + k];
        }
        float val = 2.0f * s2 - sps * anchors[k * 128 + c];
        orow[256 + e] = val;
        ss += val * val;
    }
    if (t < 256) {
        float tv = g_t[b * 256 + t];
        orow[t] = tv;
        ss += tv * tv;
    }

    __shared__ float red[32];
    __shared__ float s_inv;
    float w = warpSum(ss);
    if ((t & 31) == 0) red[t >> 5] = w;
    __syncthreads();
    if (t < 32) {
        float v = red[t];
        v = warpSum(v);
        if (t == 0) s_inv = 1.0f / fmaxf(sqrtf(v), 1e-12f);
    }
    __syncthreads();
    const float inv = s_inv;
    for (int idx = t; idx < 8448; idx += 1024) orow[idx] *= inv;
}

// ---------------------------------------------------------------------------
extern "C" void kernel_launch(void* const* d_in, const int* in_sizes, int n_in,
                              void* d_out, int out_size)
{
    const float* x       = (const float*)d_in[0];
    const float* Wf      = (const float*)d_in[1];
    const float* bf      = (const float*)d_in[2];
    const float* Ws      = (const float*)d_in[3];
    const float* bs      = (const float*)d_in[4];
    const float* Wt      = (const float*)d_in[5];
    const float* bt      = (const float*)d_in[6];
    const float* anchors = (const float*)d_in[7];
    // d_in[8] = dust_bin: constant row shift, cancels in the transport plan.
    const float* sharp   = (const float*)d_in[9];
    float* out = (float*)d_out;

    static int smem_set = 0;
    if (!smem_set) {
        cudaFuncSetAttribute(gemmA_mma, cudaFuncAttributeMaxDynamicSharedMemorySize, SM_TOTAL);
        smem_set = 1;
    }

    prepBf<<<384, 256>>>(Wf);                       // launch 0
    prepBs<<<192, 256>>>(Ws);                       // launch 1
    tG<<<32, 256>>>(x, Wt, bt);                     // launch 2
    gemmA_mma<<<dim3(8, 32), 512, SM_TOTAL>>>(x, bf, bs, sharp);  // launch 3 (ncu slot)
    expprep<<<2048, 256>>>();
    sinkhorn<<<32, 1024>>>();
    gemmC<<<dim3(8, 32), 256>>>();
    finalK<<<32, 1024>>>(anchors, out);
}

// round 8
// speedup vs baseline: 1.0678x; 1.0678x over previous
#include <cuda_runtime.h>
#include <cuda_fp16.h>
#include <math.h>
#include <stdint.h>

#define LOG2E_F 1.4426950408889634f

// ---------------- scratch (static device globals; no allocs) ----------------
__device__ float g_f[32 * 1024 * 128];       // f = fi@Wf + bf           16 MB
__device__ float g_K[32 * 64 * 1024];        // M' -> K~ (in place)       8 MB
__device__ float g_r[32 * 65];               // Sinkhorn row scalings
__device__ float g_c[32 * 1024];             // Sinkhorn col scalings
__device__ float g_vpart[32 * 8 * 64 * 128]; // split-K partials of p@f
__device__ float g_pspart[32 * 8 * 64];      // split-K partials of rowsum(p)
__device__ float g_t[32 * 256];              // t = x0 @ Wt + bt
__device__ __half g_Bhi[192 * 768];          // (W^T * 256) hi, [n][k]
__device__ __half g_Blo[192 * 768];          // (W^T * 256) lo

// ------------------------------- helpers -------------------------------------
__device__ __forceinline__ float warpSum(float v) {
    #pragma unroll
    for (int o = 16; o > 0; o >>= 1) v += __shfl_xor_sync(0xffffffffu, v, o);
    return v;
}
__device__ __forceinline__ float warpMax(float v) {
    #pragma unroll
    for (int o = 16; o > 0; o >>= 1) v = fmaxf(v, __shfl_xor_sync(0xffffffffu, v, o));
    return v;
}
// exp2 on the FMA pipe (x <= 0 here). deg-5 Taylor on [-0.5,0.5], rel err ~2e-6.
__device__ __forceinline__ float exp2_fma(float x) {
    x = fmaxf(x, -125.0f);
    int   ni = __float2int_rn(x);
    float f  = x - (float)ni;
    float p  = 1.3333558e-3f;
    p = fmaf(p, f, 9.6181290e-3f);
    p = fmaf(p, f, 5.5504109e-2f);
    p = fmaf(p, f, 2.4022651e-1f);
    p = fmaf(p, f, 6.9314718e-1f);
    p = fmaf(p, f, 1.0f);
    return p * __int_as_float((ni + 127) << 23);
}
__device__ __forceinline__ void mma16816(float* d, uint32_t a0, uint32_t a1,
                                         uint32_t a2, uint32_t a3,
                                         uint32_t b0, uint32_t b1) {
    asm volatile(
        "mma.sync.aligned.m16n8k16.row.col.f32.f16.f16.f32 "
        "{%0,%1,%2,%3}, {%4,%5,%6,%7}, {%8,%9}, {%0,%1,%2,%3};"
        : "+f"(d[0]), "+f"(d[1]), "+f"(d[2]), "+f"(d[3])
        : "r"(a0), "r"(a1), "r"(a2), "r"(a3), "r"(b0), "r"(b1));
}
__device__ __forceinline__ void ldsm4(uint32_t& r0, uint32_t& r1,
                                      uint32_t& r2, uint32_t& r3, uint32_t a) {
    asm volatile("ldmatrix.sync.aligned.m8n8.x4.shared.b16 {%0,%1,%2,%3}, [%4];"
                 : "=r"(r0), "=r"(r1), "=r"(r2), "=r"(r3) : "r"(a));
}
__device__ __forceinline__ uint32_t pack_h2(__half a, __half b) {
    __half2 h = __halves2half2(a, b);
    return *(uint32_t*)&h;
}
__device__ __forceinline__ uint32_t smem_u32(const void* p) {
    uint32_t a;
    asm("{ .reg .u64 t; cvta.to.shared.u64 t, %1; cvt.u32.u64 %0, t; }" : "=r"(a) : "l"(p));
    return a;
}
__device__ __forceinline__ void cpasync16(uint32_t dst, const void* src) {
    asm volatile("cp.async.cg.shared.global [%0], [%1], 16;" :: "r"(dst), "l"(src));
}
#define CP_COMMIT() asm volatile("cp.async.commit_group;" ::: "memory")
#define CP_WAIT0()  asm volatile("cp.async.wait_group 0;" ::: "memory")

// ------------------- prepB (split in two for launch-slot layout) -------------
__global__ __launch_bounds__(256) void prepBf(const float* __restrict__ Wf)
{
    int i = blockIdx.x * 256 + threadIdx.x;     // 128*768
    int n = i / 768, k = i - n * 768;
    float v = Wf[(size_t)k * 128 + n] * 256.0f;
    __half hi = __float2half_rn(v);
    g_Bhi[i] = hi;
    g_Blo[i] = __float2half_rn(v - __half2float(hi));
}
__global__ __launch_bounds__(256) void prepBs(const float* __restrict__ Ws)
{
    int i = blockIdx.x * 256 + threadIdx.x;     // 64*768
    int n = i / 768, k = i - n * 768;
    float v = Ws[(size_t)k * 64 + n] * 256.0f;
    __half hi = __float2half_rn(v);
    g_Bhi[128 * 768 + i] = hi;
    g_Blo[128 * 768 + i] = __float2half_rn(v - __half2float(hi));
}

// --------------------------- tG: t = x[:,0] @ Wt + bt ------------------------
__global__ __launch_bounds__(256) void tG(
    const float* __restrict__ x, const float* __restrict__ Wt,
    const float* __restrict__ bt)
{
    const int b = blockIdx.x;
    const int c = threadIdx.x;
    __shared__ float xs[768];
    for (int i = c; i < 768; i += 256) xs[i] = x[(size_t)b * 1025 * 768 + i];
    __syncthreads();
    float acc = bt[c];
    #pragma unroll 8
    for (int d = 0; d < 768; d++) acc = fmaf(xs[d], Wt[(size_t)d * 256 + c], acc);
    g_t[b * 256 + c] = acc;
}

// ---------------------------------------------------------------------------
// gemmA via mma.sync + ldmatrix. Double-buffered A-smem AND B-smem so convert
// and B-fetch overlap MMA. Balanced warp columns: each warp gets 32 f-cols
// (2-term) + 16 s-cols (3-term) = 28 HMMA/ks uniformly.
// ---------------------------------------------------------------------------
#define A_MAT  18432                         // 128 rows * 144 B
#define SMA_HI(buf) ((buf) * (2 * A_MAT))    // + lo right after
#define SMA_LO_OFF A_MAT
#define B_MAT  27648                         // 192 rows * 144 B
#define SMB_HI(buf) (4 * A_MAT + (buf) * (2 * B_MAT))
#define SMB_LO_OFF B_MAT
#define SM_TOTAL (4 * A_MAT + 4 * B_MAT)     // 184320 B

__global__ __launch_bounds__(512) void gemmA_mma(
    const float* __restrict__ x, const float* __restrict__ bf,
    const float* __restrict__ bs, const float* __restrict__ sharp)
{
    extern __shared__ char sm[];
    const uint32_t smu = smem_u32(sm);
    const int tid = threadIdx.x, wid = tid >> 5, lane = tid & 31;
    const int b = blockIdx.y, nt = blockIdx.x;
    const int wr = wid & 3, wc = wid >> 2;          // 4 x 4 warp grid
    const int g = lane >> 2, tig = lane & 3;

    // per-lane ldmatrix bases (row = lane&15, k-half = lane>>4)
    const int rl = lane & 15, kh = lane >> 4;
    const uint32_t aOff  = (uint32_t)((wr * 32 + rl) * 144 + kh * 16);
    const uint32_t bfOff = (uint32_t)((wc * 32 + rl) * 144 + kh * 16);       // f cols
    const uint32_t bsOff = (uint32_t)((128 + wc * 16 + rl) * 144 + kh * 16); // s cols

    const float* A = x + (size_t)b * 1025 * 768 + 768 + (size_t)nt * 128 * 768;
    const int am = tid >> 2, akb = (tid & 3) * 16;
    const float* aptr = A + (size_t)am * 768 + akb;
    const uint32_t cvtOff = (uint32_t)(am * 144 + akb * 2);

    float acc[2][6][4];
    #pragma unroll
    for (int mf = 0; mf < 2; mf++)
        #pragma unroll
        for (int nf = 0; nf < 6; nf++)
            #pragma unroll
            for (int q = 0; q < 4; q++) acc[mf][nf][q] = 0.0f;

    float4 aPre[4];

    // ---- convert helper (macro to keep aPre in regs) ----
    #define CONVERT_A(WBUF)                                                     \
    do {                                                                        \
        char* dhi = sm + SMA_HI(WBUF) + cvtOff;                                 \
        _Pragma("unroll")                                                       \
        for (int i = 0; i < 4; i++) {                                           \
            float4 v = aPre[i];                                                 \
            __half hx = __float2half_rn(v.x), hy = __float2half_rn(v.y);        \
            __half hz = __float2half_rn(v.z), hw = __float2half_rn(v.w);        \
            __half lx = __float2half_rn(v.x - __half2float(hx));                \
            __half ly = __float2half_rn(v.y - __half2float(hy));                \
            __half lz = __float2half_rn(v.z - __half2float(hz));                \
            __half lw = __float2half_rn(v.w - __half2float(hw));                \
            *(uint2*)(dhi + i * 8) = make_uint2(pack_h2(hx, hy), pack_h2(hz, hw)); \
            *(uint2*)(dhi + SMA_LO_OFF + i * 8) =                               \
                make_uint2(pack_h2(lx, ly), pack_h2(lz, lw));                   \
        }                                                                       \
    } while (0)

    #define FETCH_B(CH, WBUF)                                                   \
    do {                                                                        \
        const int kk0 = (CH) * 64;                                              \
        _Pragma("unroll")                                                       \
        for (int j = 0; j < 3; j++) {                                           \
            int e = tid + j * 512;                                              \
            int n = e >> 3, u = e & 7;                                          \
            uint32_t doff = (uint32_t)(n * 144 + u * 16);                       \
            cpasync16(smu + SMB_HI(WBUF) + doff, g_Bhi + (size_t)n * 768 + kk0 + u * 8); \
            cpasync16(smu + SMB_HI(WBUF) + SMB_LO_OFF + doff,                   \
                      g_Blo + (size_t)n * 768 + kk0 + u * 8);                   \
        }                                                                       \
        CP_COMMIT();                                                            \
    } while (0)

    // ---- prologue: A[0]->smem0, B[0]->bbuf0, A[1]->regs ----
    #pragma unroll
    for (int i = 0; i < 4; i++) aPre[i] = *(const float4*)(aptr + i * 4);
    FETCH_B(0, 0);
    CONVERT_A(0);
    #pragma unroll
    for (int i = 0; i < 4; i++) aPre[i] = *(const float4*)(aptr + 64 + i * 4);
    CP_WAIT0();
    __syncthreads();

    #pragma unroll 1
    for (int ch = 0; ch < 12; ch++) {
        const int buf = ch & 1;
        // ---- prefetch next chunk (overlaps the MMA below) ----
        if (ch < 11) {
            FETCH_B(ch + 1, buf ^ 1);
            CONVERT_A(buf ^ 1);
            if (ch < 10) {
                const int k2 = (ch + 2) * 64;
                #pragma unroll
                for (int i = 0; i < 4; i++) aPre[i] = *(const float4*)(aptr + k2 + i * 4);
            }
        }

        // ---- MMA on current buffers ----
        const uint32_t aHiB = smu + SMA_HI(buf) + aOff;
        const uint32_t aLoB = aHiB + SMA_LO_OFF;
        const uint32_t bHfB = smu + SMB_HI(buf) + bfOff;
        const uint32_t bHsB = smu + SMB_HI(buf) + bsOff;
        #pragma unroll
        for (int ks = 0; ks < 4; ks++) {
            const uint32_t ko = ks * 32;
            uint32_t ah[2][4], al[2][4];
            ldsm4(ah[0][0], ah[0][1], ah[0][2], ah[0][3], aHiB + ko);
            ldsm4(ah[1][0], ah[1][1], ah[1][2], ah[1][3], aHiB + 16 * 144 + ko);
            ldsm4(al[0][0], al[0][1], al[0][2], al[0][3], aLoB + ko);
            ldsm4(al[1][0], al[1][1], al[1][2], al[1][3], aLoB + 16 * 144 + ko);
            // f columns: 2 blocks of 16 cols, 2-term
            #pragma unroll
            for (int j = 0; j < 2; j++) {
                uint32_t bh0, bh1, bh2, bh3, bl0, bl1, bl2, bl3;
                ldsm4(bh0, bh1, bh2, bh3, bHfB + j * 16 * 144 + ko);
                ldsm4(bl0, bl1, bl2, bl3, bHfB + SMB_LO_OFF + j * 16 * 144 + ko);
                #pragma unroll
                for (int mf = 0; mf < 2; mf++) {
                    mma16816(acc[mf][2 * j + 0], ah[mf][0], ah[mf][1], ah[mf][2], ah[mf][3], bh0, bh2);
                    mma16816(acc[mf][2 * j + 0], ah[mf][0], ah[mf][1], ah[mf][2], ah[mf][3], bl0, bl2);
                    mma16816(acc[mf][2 * j + 1], ah[mf][0], ah[mf][1], ah[mf][2], ah[mf][3], bh1, bh3);
                    mma16816(acc[mf][2 * j + 1], ah[mf][0], ah[mf][1], ah[mf][2], ah[mf][3], bl1, bl3);
                }
            }
            // s columns: 1 block of 16 cols, 3-term
            {
                uint32_t bh0, bh1, bh2, bh3, bl0, bl1, bl2, bl3;
                ldsm4(bh0, bh1, bh2, bh3, bHsB + ko);
                ldsm4(bl0, bl1, bl2, bl3, bHsB + SMB_LO_OFF + ko);
                #pragma unroll
                for (int mf = 0; mf < 2; mf++) {
                    mma16816(acc[mf][4], ah[mf][0], ah[mf][1], ah[mf][2], ah[mf][3], bh0, bh2);
                    mma16816(acc[mf][4], ah[mf][0], ah[mf][1], ah[mf][2], ah[mf][3], bl0, bl2);
                    mma16816(acc[mf][4], al[mf][0], al[mf][1], al[mf][2], al[mf][3], bh0, bh2);
                    mma16816(acc[mf][5], ah[mf][0], ah[mf][1], ah[mf][2], ah[mf][3], bh1, bh3);
                    mma16816(acc[mf][5], ah[mf][0], ah[mf][1], ah[mf][2], ah[mf][3], bl1, bl3);
                    mma16816(acc[mf][5], al[mf][0], al[mf][1], al[mf][2], al[mf][3], bh1, bh3);
                }
            }
        }
        if (ch < 11) CP_WAIT0();
        __syncthreads();
    }

    // ---------------------------- epilogue ----------------------------------
    const float inv256 = 1.0f / 256.0f;
    const float scl = sharp[0] * 10.0f * LOG2E_F;   // sharpness/REG * log2(e)
    #pragma unroll
    for (int mf = 0; mf < 2; mf++) {
        // f part: nf 0..3 -> col = wc*32 + nf*8 + tig*2
        #pragma unroll
        for (int nf = 0; nf < 4; nf++) {
            int c = wc * 32 + nf * 8 + tig * 2;
            int r0 = nt * 128 + wr * 32 + mf * 16 + g;
            int r1 = r0 + 8;
            float b0 = __ldg(bf + c), b1 = __ldg(bf + c + 1);
            *(float2*)(g_f + ((size_t)(b * 1024 + r0)) * 128 + c) =
                make_float2(fmaf(acc[mf][nf][0], inv256, b0), fmaf(acc[mf][nf][1], inv256, b1));
            *(float2*)(g_f + ((size_t)(b * 1024 + r1)) * 128 + c) =
                make_float2(fmaf(acc[mf][nf][2], inv256, b0), fmaf(acc[mf][nf][3], inv256, b1));
        }
        // s part: nf 4..5 -> k = wc*16 + (nf-4)*8 + tig*2
        #pragma unroll
        for (int nf = 4; nf < 6; nf++) {
            int k = wc * 16 + (nf - 4) * 8 + tig * 2;
            int r0 = nt * 128 + wr * 32 + mf * 16 + g;
            int r1 = r0 + 8;
            float b0 = __ldg(bs + k), b1 = __ldg(bs + k + 1);
            float* K0 = g_K + ((size_t)(b * 64 + k)) * 1024;
            float* K1 = g_K + ((size_t)(b * 64 + k + 1)) * 1024;
            K0[r0] = fmaf(acc[mf][nf][0], inv256, b0) * scl;
            K1[r0] = fmaf(acc[mf][nf][1], inv256, b1) * scl;
            K0[r1] = fmaf(acc[mf][nf][2], inv256, b0) * scl;
            K1[r1] = fmaf(acc[mf][nf][3], inv256, b1) * scl;
        }
    }
}

// ------------- expprep: rowmax + exp2 + rowsum -> initial r ------------------
__global__ __launch_bounds__(256) void expprep()
{
    const int row = blockIdx.x;              // b*64 + k
    float4* p = (float4*)(g_K + ((size_t)row << 10));
    const int t = threadIdx.x;
    float4 v = p[t];
    __shared__ float red[8];
    __shared__ float s_bm;
    float mx = fmaxf(fmaxf(v.x, v.y), fmaxf(v.z, v.w));
    mx = warpMax(mx);
    if ((t & 31) == 0) red[t >> 5] = mx;
    __syncthreads();
    if (t == 0) {
        float mm = red[0];
        #pragma unroll
        for (int i = 1; i < 8; i++) mm = fmaxf(mm, red[i]);
        s_bm = mm;
    }
    __syncthreads();
    const float m = s_bm;
    v.x = exp2_fma(v.x - m); v.y = exp2_fma(v.y - m);
    v.z = exp2_fma(v.z - m); v.w = exp2_fma(v.w - m);
    p[t] = v;
    float s = (v.x + v.y) + (v.z + v.w);
    s = warpSum(s);
    if ((t & 31) == 0) red[t >> 5] = s;
    __syncthreads();
    if (t == 0) {
        float tot = 0.0f;
        #pragma unroll
        for (int i = 0; i < 8; i++) tot += red[i];
        g_r[(row >> 6) * 65 + (row & 63)] = (1.0f / 65.0f) / tot;
        if ((row & 63) == 0) g_r[(row >> 6) * 65 + 64] = (1.0f / 65.0f) / 1024.0f;
    }
}

// ------------- fused Sinkhorn: 5 c-updates + 4 r-updates, one launch ---------
__global__ __launch_bounds__(1024) void sinkhorn()
{
    const int b = blockIdx.x;
    const int t = threadIdx.x, w = t >> 5, l = t & 31;
    __shared__ float cs[1024];
    __shared__ float rs[72];
    __shared__ float red[32];
    if (t < 65) rs[t] = g_r[b * 65 + t];
    __syncthreads();
    const float* Kb = g_K + ((size_t)b << 16);

    #pragma unroll 1
    for (int it = 0; it < 5; it++) {
        const float* col = Kb + t;
        float a0 = rs[64], a1 = 0.f, a2 = 0.f, a3 = 0.f;
        float a4 = 0.f, a5 = 0.f, a6 = 0.f, a7 = 0.f;
        #pragma unroll
        for (int k = 0; k < 64; k += 8) {
            a0 = fmaf(col[(size_t)(k + 0) << 10], rs[k + 0], a0);
            a1 = fmaf(col[(size_t)(k + 1) << 10], rs[k + 1], a1);
            a2 = fmaf(col[(size_t)(k + 2) << 10], rs[k + 2], a2);
            a3 = fmaf(col[(size_t)(k + 3) << 10], rs[k + 3], a3);
            a4 = fmaf(col[(size_t)(k + 4) << 10], rs[k + 4], a4);
            a5 = fmaf(col[(size_t)(k + 5) << 10], rs[k + 5], a5);
            a6 = fmaf(col[(size_t)(k + 6) << 10], rs[k + 6], a6);
            a7 = fmaf(col[(size_t)(k + 7) << 10], rs[k + 7], a7);
        }
        float cv = (1.0f / 1024.0f) /
                   (((a0 + a1) + (a2 + a3)) + ((a4 + a5) + (a6 + a7)));
        cs[t] = cv;
        float sw = warpSum(cv);
        if (l == 0) red[w] = sw;
        __syncthreads();
        if (it < 4) {
            if (t == 0) {
                float s = 0.0f;
                #pragma unroll
                for (int i = 0; i < 32; i++) s += red[i];
                rs[64] = (1.0f / 65.0f) / s;
            }
            #pragma unroll
            for (int rr = 0; rr < 2; rr++) {
                int k = w + rr * 32;
                const float* row = Kb + ((size_t)k << 10);
                float d0 = 0.f, d1 = 0.f, d2 = 0.f, d3 = 0.f;
                float d4 = 0.f, d5 = 0.f, d6 = 0.f, d7 = 0.f;
                #pragma unroll
                for (int n0 = 0; n0 < 1024; n0 += 256) {
                    d0 = fmaf(row[n0 + l],        cs[n0 + l],        d0);
                    d1 = fmaf(row[n0 + l + 32],   cs[n0 + l + 32],   d1);
                    d2 = fmaf(row[n0 + l + 64],   cs[n0 + l + 64],   d2);
                    d3 = fmaf(row[n0 + l + 96],   cs[n0 + l + 96],   d3);
                    d4 = fmaf(row[n0 + l + 128],  cs[n0 + l + 128],  d4);
                    d5 = fmaf(row[n0 + l + 160],  cs[n0 + l + 160],  d5);
                    d6 = fmaf(row[n0 + l + 192],  cs[n0 + l + 192],  d6);
                    d7 = fmaf(row[n0 + l + 224],  cs[n0 + l + 224],  d7);
                }
                float d = warpSum((((d0 + d1) + (d2 + d3)) + ((d4 + d5) + (d6 + d7))));
                if (l == 0) rs[k] = (1.0f / 65.0f) / d;
            }
            __syncthreads();
        }
    }
    g_c[b * 1024 + t] = cs[t];
    if (t < 65) g_r[b * 65 + t] = rs[t];
}

// ---------------------------------------------------------------------------
// GEMM C: partial (64x128) = p_slice @ f_slice, p materialized as K~ * r * c.
// ---------------------------------------------------------------------------
__global__ __launch_bounds__(256) void gemmC()
{
    const int b = blockIdx.y, sp = blockIdx.x;
    const int tid = threadIdx.x;
    const int tx = tid & 15, ty = tid >> 4;
    __shared__ float ps[64][33];
    __shared__ float fs[32][128];

    const int n0 = sp * 128;
    float acc[4][8];
    #pragma unroll
    for (int i = 0; i < 4; i++)
        #pragma unroll
        for (int j = 0; j < 8; j++) acc[i][j] = 0.0f;
    float psum = 0.0f;

    for (int c0 = 0; c0 < 128; c0 += 32) {
        __syncthreads();
        #pragma unroll
        for (int j = 0; j < 2; j++) {
            int idx4 = tid + j * 256;
            int k = idx4 >> 3;
            int nn4 = (idx4 & 7) * 4;
            float4 kv = *(const float4*)(g_K + ((size_t)(b * 64 + k)) * 1024 + n0 + c0 + nn4);
            float4 cv = *(const float4*)(g_c + b * 1024 + n0 + c0 + nn4);
            float rv = __ldg(&g_r[b * 65 + k]);
            ps[k][nn4 + 0] = kv.x * cv.x * rv;
            ps[k][nn4 + 1] = kv.y * cv.y * rv;
            ps[k][nn4 + 2] = kv.z * cv.z * rv;
            ps[k][nn4 + 3] = kv.w * cv.w * rv;
        }
        #pragma unroll
        for (int j = 0; j < 4; j++) {
            int idx4 = tid + j * 256;
            int nn = idx4 >> 5;
            int c4 = (idx4 & 31) * 4;
            *(float4*)&fs[nn][c4] =
                *(const float4*)(g_f + ((size_t)(b * 1024 + n0 + c0 + nn)) * 128 + c4);
        }
        __syncthreads();

        #pragma unroll
        for (int nn = 0; nn < 32; nn++) {
            float a4[4];
            #pragma unroll
            for (int i = 0; i < 4; i++) a4[i] = ps[ty * 4 + i][nn];
            float4 b0 = *(const float4*)&fs[nn][tx * 8];
            float4 b1 = *(const float4*)&fs[nn][tx * 8 + 4];
            float b8[8] = {b0.x, b0.y, b0.z, b0.w, b1.x, b1.y, b1.z, b1.w};
            #pragma unroll
            for (int i = 0; i < 4; i++)
                #pragma unroll
                for (int j = 0; j < 8; j++)
                    acc[i][j] = fmaf(a4[i], b8[j], acc[i][j]);
        }

        if (tid < 64) {
            float s = 0.0f;
            #pragma unroll
            for (int nn = 0; nn < 32; nn++) s += ps[tid][nn];
            psum += s;
        }
    }

    #pragma unroll
    for (int i = 0; i < 4; i++) {
        float* dst = g_vpart + (((size_t)(b * 8 + sp) * 64) + ty * 4 + i) * 128 + tx * 8;
        *(float4*)(dst)     = make_float4(acc[i][0], acc[i][1], acc[i][2], acc[i][3]);
        *(float4*)(dst + 4) = make_float4(acc[i][4], acc[i][5], acc[i][6], acc[i][7]);
    }
    if (tid < 64) g_pspart[(b * 8 + sp) * 64 + tid] = psum;
}

// ----- finalK: split-K reduce + anchors + t concat + L2 normalize ------------
__global__ __launch_bounds__(1024) void finalK(
    const float* __restrict__ anchors, float* __restrict__ out)
{
    const int b = blockIdx.x, t = threadIdx.x;
    float* orow = out + (size_t)b * 8448;
    float ss = 0.0f;

    #pragma unroll
    for (int j = 0; j < 8; j++) {
        int e = t + j * 1024;
        int k = e >> 7, c = e & 127;
        float s2 = 0.0f, sps = 0.0f;
        #pragma unroll
        for (int sp = 0; sp < 8; sp++) {
            s2  += g_vpart[(((size_t)(b * 8 + sp) * 64) + k) * 128 + c];
            sps += g_pspart[(b * 8 + sp) * 64 + k];
        }
        float val = 2.0f * s2 - sps * anchors[k * 128 + c];
        orow[256 + e] = val;
        ss += val * val;
    }
    if (t < 256) {
        float tv = g_t[b * 256 + t];
        orow[t] = tv;
        ss += tv * tv;
    }

    __shared__ float red[32];
    __shared__ float s_inv;
    float w = warpSum(ss);
    if ((t & 31) == 0) red[t >> 5] = w;
    __syncthreads();
    if (t < 32) {
        float v = red[t];
        v = warpSum(v);
        if (t == 0) s_inv = 1.0f / fmaxf(sqrtf(v), 1e-12f);
    }
    __syncthreads();
    const float inv = s_inv;
    for (int idx = t; idx < 8448; idx += 1024) orow[idx] *= inv;
}

// ---------------------------------------------------------------------------
extern "C" void kernel_launch(void* const* d_in, const int* in_sizes, int n_in,
                              void* d_out, int out_size)
{
    const float* x       = (const float*)d_in[0];
    const float* Wf      = (const float*)d_in[1];
    const float* bf      = (const float*)d_in[2];
    const float* Ws      = (const float*)d_in[3];
    const float* bs      = (const float*)d_in[4];
    const float* Wt      = (const float*)d_in[5];
    const float* bt      = (const float*)d_in[6];
    const float* anchors = (const float*)d_in[7];
    // d_in[8] = dust_bin: constant row shift, cancels in the transport plan.
    const float* sharp   = (const float*)d_in[9];
    float* out = (float*)d_out;

    static int smem_set = 0;
    if (!smem_set) {
        cudaFuncSetAttribute(gemmA_mma, cudaFuncAttributeMaxDynamicSharedMemorySize, SM_TOTAL);
        smem_set = 1;
    }

    prepBf<<<384, 256>>>(Wf);                       // launch 0
    prepBs<<<192, 256>>>(Ws);                       // launch 1
    tG<<<32, 256>>>(x, Wt, bt);                     // launch 2
    gemmA_mma<<<dim3(8, 32), 512, SM_TOTAL>>>(x, bf, bs, sharp);  // launch 3 (ncu slot)
    expprep<<<2048, 256>>>();
    sinkhorn<<<32, 1024>>>();
    gemmC<<<dim3(8, 32), 256>>>();
    finalK<<<32, 1024>>>(anchors, out);
}

// round 9
// speedup vs baseline: 1.1729x; 1.0985x over previous
#include <cuda_runtime.h>
#include <cuda_fp16.h>
#include <math.h>
#include <stdint.h>

#define LOG2E_F 1.4426950408889634f

// ---------------- scratch (static device globals; no allocs) ----------------
__device__ float g_f[32 * 1024 * 128];       // f = fi@Wf + bf           16 MB
__device__ float g_K[32 * 64 * 1024];        // M' -> K~ (in place)       8 MB
__device__ float g_r[32 * 65];               // Sinkhorn row scalings
__device__ float g_c[32 * 1024];             // Sinkhorn col scalings
__device__ float g_vpart[32 * 8 * 64 * 128]; // split-K partials of p@f
__device__ float g_pspart[32 * 8 * 64];      // split-K partials of rowsum(p)
__device__ float g_t[32 * 256];              // t = x0 @ Wt + bt
__device__ __half g_Bhi[192 * 768];          // (W^T * 256) hi, [n][k]
__device__ __half g_Blo[192 * 768];          // (W^T * 256) lo (s rows at 128..191)

// ------------------------------- helpers -------------------------------------
__device__ __forceinline__ float warpSum(float v) {
    #pragma unroll
    for (int o = 16; o > 0; o >>= 1) v += __shfl_xor_sync(0xffffffffu, v, o);
    return v;
}
__device__ __forceinline__ float warpMax(float v) {
    #pragma unroll
    for (int o = 16; o > 0; o >>= 1) v = fmaxf(v, __shfl_xor_sync(0xffffffffu, v, o));
    return v;
}
// exp2 on the FMA pipe (x <= 0 here). deg-5 Taylor on [-0.5,0.5], rel err ~2e-6.
__device__ __forceinline__ float exp2_fma(float x) {
    x = fmaxf(x, -125.0f);
    int   ni = __float2int_rn(x);
    float f  = x - (float)ni;
    float p  = 1.3333558e-3f;
    p = fmaf(p, f, 9.6181290e-3f);
    p = fmaf(p, f, 5.5504109e-2f);
    p = fmaf(p, f, 2.4022651e-1f);
    p = fmaf(p, f, 6.9314718e-1f);
    p = fmaf(p, f, 1.0f);
    return p * __int_as_float((ni + 127) << 23);
}
__device__ __forceinline__ void mma16816(float* d, uint32_t a0, uint32_t a1,
                                         uint32_t a2, uint32_t a3,
                                         uint32_t b0, uint32_t b1) {
    asm volatile(
        "mma.sync.aligned.m16n8k16.row.col.f32.f16.f16.f32 "
        "{%0,%1,%2,%3}, {%4,%5,%6,%7}, {%8,%9}, {%0,%1,%2,%3};"
        : "+f"(d[0]), "+f"(d[1]), "+f"(d[2]), "+f"(d[3])
        : "r"(a0), "r"(a1), "r"(a2), "r"(a3), "r"(b0), "r"(b1));
}
__device__ __forceinline__ void ldsm4(uint32_t& r0, uint32_t& r1,
                                      uint32_t& r2, uint32_t& r3, uint32_t a) {
    asm volatile("ldmatrix.sync.aligned.m8n8.x4.shared.b16 {%0,%1,%2,%3}, [%4];"
                 : "=r"(r0), "=r"(r1), "=r"(r2), "=r"(r3) : "r"(a));
}
__device__ __forceinline__ uint32_t pack_h2(__half a, __half b) {
    __half2 h = __halves2half2(a, b);
    return *(uint32_t*)&h;
}
__device__ __forceinline__ uint32_t smem_u32(const void* p) {
    uint32_t a;
    asm("{ .reg .u64 t; cvta.to.shared.u64 t, %1; cvt.u32.u64 %0, t; }" : "=r"(a) : "l"(p));
    return a;
}
__device__ __forceinline__ void cpasync16(uint32_t dst, const void* src) {
    asm volatile("cp.async.cg.shared.global [%0], [%1], 16;" :: "r"(dst), "l"(src));
}
#define CP_COMMIT() asm volatile("cp.async.commit_group;" ::: "memory")
#define CP_WAIT0()  asm volatile("cp.async.wait_group 0;" ::: "memory")

// ------------------- prepB (split in two for launch-slot layout) -------------
__global__ __launch_bounds__(256) void prepBf(const float* __restrict__ Wf)
{
    int i = blockIdx.x * 256 + threadIdx.x;     // 128*768
    int n = i / 768, k = i - n * 768;
    float v = Wf[(size_t)k * 128 + n] * 256.0f;
    __half hi = __float2half_rn(v);
    g_Bhi[i] = hi;
    g_Blo[i] = __float2half_rn(v - __half2float(hi));
}
__global__ __launch_bounds__(256) void prepBs(const float* __restrict__ Ws)
{
    int i = blockIdx.x * 256 + threadIdx.x;     // 64*768
    int n = i / 768, k = i - n * 768;
    float v = Ws[(size_t)k * 64 + n] * 256.0f;
    __half hi = __float2half_rn(v);
    g_Bhi[128 * 768 + i] = hi;
    g_Blo[128 * 768 + i] = __float2half_rn(v - __half2float(hi));
}

// --------------------------- tG: t = x[:,0] @ Wt + bt ------------------------
__global__ __launch_bounds__(256) void tG(
    const float* __restrict__ x, const float* __restrict__ Wt,
    const float* __restrict__ bt)
{
    const int b = blockIdx.x;
    const int c = threadIdx.x;
    __shared__ float xs[768];
    for (int i = c; i < 768; i += 256) xs[i] = x[(size_t)b * 1025 * 768 + i];
    __syncthreads();
    float acc = bt[c];
    #pragma unroll 8
    for (int d = 0; d < 768; d++) acc = fmaf(xs[d], Wt[(size_t)d * 256 + c], acc);
    g_t[b * 256 + c] = acc;
}

// ---------------------------------------------------------------------------
// gemmA via mma.sync + ldmatrix, double-buffered A and B smem.
// f cols (0..127): 1-term (Ahi*Bhi).  s cols (128..191): 3-term.
// Per warp per ks: 8 f-MMA + 12 s-MMA = 20 HMMA, balanced across warps.
// B smem per buffer: 192 hi rows + 64 s-lo rows (36,864 B).
// ---------------------------------------------------------------------------
#define A_MAT  18432                          // 128 rows * 144 B
#define SMA_HI(buf) ((buf) * (2 * A_MAT))
#define SMA_LO_OFF A_MAT
#define B_HI_SZ 27648                         // 192 * 144
#define B_LOS_SZ 9216                         // 64 * 144
#define B_BUF (B_HI_SZ + B_LOS_SZ)            // 36864
#define SMB_HI(buf) (4 * A_MAT + (buf) * B_BUF)
#define SMB_LOS_OFF B_HI_SZ
#define SM_TOTAL (4 * A_MAT + 2 * B_BUF)      // 147456 B

__global__ __launch_bounds__(512) void gemmA_mma(
    const float* __restrict__ x, const float* __restrict__ bf,
    const float* __restrict__ bs, const float* __restrict__ sharp)
{
    extern __shared__ char sm[];
    const uint32_t smu = smem_u32(sm);
    const int tid = threadIdx.x, wid = tid >> 5, lane = tid & 31;
    const int b = blockIdx.y, nt = blockIdx.x;
    const int wr = wid & 3, wc = wid >> 2;          // 4 x 4 warp grid
    const int g = lane >> 2, tig = lane & 3;

    // per-lane ldmatrix bases (row = lane&15, k-half = lane>>4)
    const int rl = lane & 15, kh = lane >> 4;
    const uint32_t aOff   = (uint32_t)((wr * 32 + rl) * 144 + kh * 16);
    const uint32_t bfOff  = (uint32_t)((wc * 32 + rl) * 144 + kh * 16);        // f-hi
    const uint32_t bshOff = (uint32_t)((128 + wc * 16 + rl) * 144 + kh * 16);  // s-hi
    const uint32_t bslOff = (uint32_t)(SMB_LOS_OFF + (wc * 16 + rl) * 144 + kh * 16); // s-lo

    const float* A = x + (size_t)b * 1025 * 768 + 768 + (size_t)nt * 128 * 768;
    const int am = tid >> 2, akb = (tid & 3) * 16;
    const float* aptr = A + (size_t)am * 768 + akb;
    const uint32_t cvtOff = (uint32_t)(am * 144 + akb * 2);

    float acc[2][6][4];        // [mf][nf<4: f cols | nf 4,5: s cols]
    float accS2[2][2][4];      // second accumulator set for s cols
    #pragma unroll
    for (int mf = 0; mf < 2; mf++) {
        #pragma unroll
        for (int nf = 0; nf < 6; nf++)
            #pragma unroll
            for (int q = 0; q < 4; q++) acc[mf][nf][q] = 0.0f;
        #pragma unroll
        for (int nf = 0; nf < 2; nf++)
            #pragma unroll
            for (int q = 0; q < 4; q++) accS2[mf][nf][q] = 0.0f;
    }

    float4 aPre[4];

    #define CONVERT_A(WBUF)                                                     \
    do {                                                                        \
        char* dhi = sm + SMA_HI(WBUF) + cvtOff;                                 \
        _Pragma("unroll")                                                       \
        for (int i = 0; i < 4; i++) {                                           \
            float4 v = aPre[i];                                                 \
            __half hx = __float2half_rn(v.x), hy = __float2half_rn(v.y);        \
            __half hz = __float2half_rn(v.z), hw = __float2half_rn(v.w);        \
            __half lx = __float2half_rn(v.x - __half2float(hx));                \
            __half ly = __float2half_rn(v.y - __half2float(hy));                \
            __half lz = __float2half_rn(v.z - __half2float(hz));                \
            __half lw = __float2half_rn(v.w - __half2float(hw));                \
            *(uint2*)(dhi + i * 8) = make_uint2(pack_h2(hx, hy), pack_h2(hz, hw)); \
            *(uint2*)(dhi + SMA_LO_OFF + i * 8) =                               \
                make_uint2(pack_h2(lx, ly), pack_h2(lz, lw));                   \
        }                                                                       \
    } while (0)

    #define FETCH_B(CH, WBUF)                                                   \
    do {                                                                        \
        const int kk0 = (CH) * 64;                                              \
        _Pragma("unroll")                                                       \
        for (int j = 0; j < 3; j++) {     /* B-hi: 192 rows */                  \
            int e = tid + j * 512;                                              \
            int n = e >> 3, u = e & 7;                                          \
            cpasync16(smu + SMB_HI(WBUF) + (uint32_t)(n * 144 + u * 16),        \
                      g_Bhi + (size_t)n * 768 + kk0 + u * 8);                   \
        }                                                                       \
        {                                  /* B-lo: s rows only (64) */         \
            int n = tid >> 3, u = tid & 7;                                      \
            if (n < 64)                                                         \
                cpasync16(smu + SMB_HI(WBUF) + SMB_LOS_OFF +                    \
                          (uint32_t)(n * 144 + u * 16),                         \
                          g_Blo + (size_t)(128 + n) * 768 + kk0 + u * 8);       \
        }                                                                       \
        CP_COMMIT();                                                            \
    } while (0)

    // ---- prologue ----
    #pragma unroll
    for (int i = 0; i < 4; i++) aPre[i] = *(const float4*)(aptr + i * 4);
    FETCH_B(0, 0);
    CONVERT_A(0);
    #pragma unroll
    for (int i = 0; i < 4; i++) aPre[i] = *(const float4*)(aptr + 64 + i * 4);
    CP_WAIT0();
    __syncthreads();

    #pragma unroll 1
    for (int ch = 0; ch < 12; ch++) {
        const int buf = ch & 1;
        if (ch < 11) {
            FETCH_B(ch + 1, buf ^ 1);
            CONVERT_A(buf ^ 1);
            if (ch < 10) {
                const int k2 = (ch + 2) * 64;
                #pragma unroll
                for (int i = 0; i < 4; i++) aPre[i] = *(const float4*)(aptr + k2 + i * 4);
            }
        }

        const uint32_t aHiB = smu + SMA_HI(buf) + aOff;
        const uint32_t aLoB = aHiB + SMA_LO_OFF;
        const uint32_t bHfB = smu + SMB_HI(buf) + bfOff;
        const uint32_t bHsB = smu + SMB_HI(buf) + bshOff;
        const uint32_t bLsB = smu + SMB_HI(buf) + bslOff;
        #pragma unroll
        for (int ks = 0; ks < 4; ks++) {
            const uint32_t ko = ks * 32;
            uint32_t ah[2][4], al[2][4];
            uint32_t bsh0, bsh1, bsh2, bsh3, bsl0, bsl1, bsl2, bsl3;
            uint32_t bf0[4], bf1[4];
            ldsm4(ah[0][0], ah[0][1], ah[0][2], ah[0][3], aHiB + ko);
            ldsm4(ah[1][0], ah[1][1], ah[1][2], ah[1][3], aHiB + 16 * 144 + ko);
            ldsm4(bsh0, bsh1, bsh2, bsh3, bHsB + ko);
            ldsm4(al[0][0], al[0][1], al[0][2], al[0][3], aLoB + ko);
            ldsm4(al[1][0], al[1][1], al[1][2], al[1][3], aLoB + 16 * 144 + ko);
            ldsm4(bsl0, bsl1, bsl2, bsl3, bLsB + ko);
            ldsm4(bf0[0], bf0[1], bf0[2], bf0[3], bHfB + ko);
            ldsm4(bf1[0], bf1[1], bf1[2], bf1[3], bHfB + 16 * 144 + ko);

            // s term 1 (ahi * bs_hi) -> acc[.][4,5]
            mma16816(acc[0][4], ah[0][0], ah[0][1], ah[0][2], ah[0][3], bsh0, bsh2);
            mma16816(acc[0][5], ah[0][0], ah[0][1], ah[0][2], ah[0][3], bsh1, bsh3);
            mma16816(acc[1][4], ah[1][0], ah[1][1], ah[1][2], ah[1][3], bsh0, bsh2);
            mma16816(acc[1][5], ah[1][0], ah[1][1], ah[1][2], ah[1][3], bsh1, bsh3);
            // f block 0 (1-term)
            mma16816(acc[0][0], ah[0][0], ah[0][1], ah[0][2], ah[0][3], bf0[0], bf0[2]);
            mma16816(acc[0][1], ah[0][0], ah[0][1], ah[0][2], ah[0][3], bf0[1], bf0[3]);
            mma16816(acc[1][0], ah[1][0], ah[1][1], ah[1][2], ah[1][3], bf0[0], bf0[2]);
            mma16816(acc[1][1], ah[1][0], ah[1][1], ah[1][2], ah[1][3], bf0[1], bf0[3]);
            // s term 2 (ahi * bs_lo) -> accS2
            mma16816(accS2[0][0], ah[0][0], ah[0][1], ah[0][2], ah[0][3], bsl0, bsl2);
            mma16816(accS2[0][1], ah[0][0], ah[0][1], ah[0][2], ah[0][3], bsl1, bsl3);
            mma16816(accS2[1][0], ah[1][0], ah[1][1], ah[1][2], ah[1][3], bsl0, bsl2);
            mma16816(accS2[1][1], ah[1][0], ah[1][1], ah[1][2], ah[1][3], bsl1, bsl3);
            // f block 1 (1-term)
            mma16816(acc[0][2], ah[0][0], ah[0][1], ah[0][2], ah[0][3], bf1[0], bf1[2]);
            mma16816(acc[0][3], ah[0][0], ah[0][1], ah[0][2], ah[0][3], bf1[1], bf1[3]);
            mma16816(acc[1][2], ah[1][0], ah[1][1], ah[1][2], ah[1][3], bf1[0], bf1[2]);
            mma16816(acc[1][3], ah[1][0], ah[1][1], ah[1][2], ah[1][3], bf1[1], bf1[3]);
            // s term 3 (alo * bs_hi) -> acc[.][4,5]  (12 MMAs after term 1)
            mma16816(acc[0][4], al[0][0], al[0][1], al[0][2], al[0][3], bsh0, bsh2);
            mma16816(acc[0][5], al[0][0], al[0][1], al[0][2], al[0][3], bsh1, bsh3);
            mma16816(acc[1][4], al[1][0], al[1][1], al[1][2], al[1][3], bsh0, bsh2);
            mma16816(acc[1][5], al[1][0], al[1][1], al[1][2], al[1][3], bsh1, bsh3);
        }
        if (ch < 11) CP_WAIT0();
        __syncthreads();
    }

    // ---------------------------- epilogue ----------------------------------
    const float inv256 = 1.0f / 256.0f;
    const float scl = sharp[0] * 10.0f * LOG2E_F;   // sharpness/REG * log2(e)
    #pragma unroll
    for (int mf = 0; mf < 2; mf++) {
        #pragma unroll
        for (int nf = 0; nf < 4; nf++) {
            int c = wc * 32 + nf * 8 + tig * 2;
            int r0 = nt * 128 + wr * 32 + mf * 16 + g;
            int r1 = r0 + 8;
            float b0 = __ldg(bf + c), b1 = __ldg(bf + c + 1);
            *(float2*)(g_f + ((size_t)(b * 1024 + r0)) * 128 + c) =
                make_float2(fmaf(acc[mf][nf][0], inv256, b0), fmaf(acc[mf][nf][1], inv256, b1));
            *(float2*)(g_f + ((size_t)(b * 1024 + r1)) * 128 + c) =
                make_float2(fmaf(acc[mf][nf][2], inv256, b0), fmaf(acc[mf][nf][3], inv256, b1));
        }
        #pragma unroll
        for (int nf = 4; nf < 6; nf++) {
            int k = wc * 16 + (nf - 4) * 8 + tig * 2;
            int r0 = nt * 128 + wr * 32 + mf * 16 + g;
            int r1 = r0 + 8;
            float b0 = __ldg(bs + k), b1 = __ldg(bs + k + 1);
            float* K0 = g_K + ((size_t)(b * 64 + k)) * 1024;
            float* K1 = g_K + ((size_t)(b * 64 + k + 1)) * 1024;
            float d0 = acc[mf][nf][0] + accS2[mf][nf - 4][0];
            float d1 = acc[mf][nf][1] + accS2[mf][nf - 4][1];
            float d2 = acc[mf][nf][2] + accS2[mf][nf - 4][2];
            float d3 = acc[mf][nf][3] + accS2[mf][nf - 4][3];
            K0[r0] = fmaf(d0, inv256, b0) * scl;
            K1[r0] = fmaf(d1, inv256, b1) * scl;
            K0[r1] = fmaf(d2, inv256, b0) * scl;
            K1[r1] = fmaf(d3, inv256, b1) * scl;
        }
    }
}

// ------------- expprep: rowmax + exp2 + rowsum -> initial r ------------------
__global__ __launch_bounds__(256) void expprep()
{
    const int row = blockIdx.x;              // b*64 + k
    float4* p = (float4*)(g_K + ((size_t)row << 10));
    const int t = threadIdx.x;
    float4 v = p[t];
    __shared__ float red[8];
    __shared__ float s_bm;
    float mx = fmaxf(fmaxf(v.x, v.y), fmaxf(v.z, v.w));
    mx = warpMax(mx);
    if ((t & 31) == 0) red[t >> 5] = mx;
    __syncthreads();
    if (t == 0) {
        float mm = red[0];
        #pragma unroll
        for (int i = 1; i < 8; i++) mm = fmaxf(mm, red[i]);
        s_bm = mm;
    }
    __syncthreads();
    const float m = s_bm;
    v.x = exp2_fma(v.x - m); v.y = exp2_fma(v.y - m);
    v.z = exp2_fma(v.z - m); v.w = exp2_fma(v.w - m);
    p[t] = v;
    float s = (v.x + v.y) + (v.z + v.w);
    s = warpSum(s);
    if ((t & 31) == 0) red[t >> 5] = s;
    __syncthreads();
    if (t == 0) {
        float tot = 0.0f;
        #pragma unroll
        for (int i = 0; i < 8; i++) tot += red[i];
        g_r[(row >> 6) * 65 + (row & 63)] = (1.0f / 65.0f) / tot;
        if ((row & 63) == 0) g_r[(row >> 6) * 65 + 64] = (1.0f / 65.0f) / 1024.0f;
    }
}

// ------------- fused Sinkhorn: 5 c-updates + 4 r-updates, one launch ---------
__global__ __launch_bounds__(1024) void sinkhorn()
{
    const int b = blockIdx.x;
    const int t = threadIdx.x, w = t >> 5, l = t & 31;
    __shared__ float cs[1024];
    __shared__ float rs[72];
    __shared__ float red[32];
    if (t < 65) rs[t] = g_r[b * 65 + t];
    __syncthreads();
    const float* Kb = g_K + ((size_t)b << 16);

    #pragma unroll 1
    for (int it = 0; it < 5; it++) {
        const float* col = Kb + t;
        float a0 = rs[64], a1 = 0.f, a2 = 0.f, a3 = 0.f;
        float a4 = 0.f, a5 = 0.f, a6 = 0.f, a7 = 0.f;
        #pragma unroll
        for (int k = 0; k < 64; k += 8) {
            a0 = fmaf(col[(size_t)(k + 0) << 10], rs[k + 0], a0);
            a1 = fmaf(col[(size_t)(k + 1) << 10], rs[k + 1], a1);
            a2 = fmaf(col[(size_t)(k + 2) << 10], rs[k + 2], a2);
            a3 = fmaf(col[(size_t)(k + 3) << 10], rs[k + 3], a3);
            a4 = fmaf(col[(size_t)(k + 4) << 10], rs[k + 4], a4);
            a5 = fmaf(col[(size_t)(k + 5) << 10], rs[k + 5], a5);
            a6 = fmaf(col[(size_t)(k + 6) << 10], rs[k + 6], a6);
            a7 = fmaf(col[(size_t)(k + 7) << 10], rs[k + 7], a7);
        }
        float cv = (1.0f / 1024.0f) /
                   (((a0 + a1) + (a2 + a3)) + ((a4 + a5) + (a6 + a7)));
        cs[t] = cv;
        float sw = warpSum(cv);
        if (l == 0) red[w] = sw;
        __syncthreads();
        if (it < 4) {
            if (t == 0) {
                float s = 0.0f;
                #pragma unroll
                for (int i = 0; i < 32; i++) s += red[i];
                rs[64] = (1.0f / 65.0f) / s;
            }
            #pragma unroll
            for (int rr = 0; rr < 2; rr++) {
                int k = w + rr * 32;
                const float* row = Kb + ((size_t)k << 10);
                float d0 = 0.f, d1 = 0.f, d2 = 0.f, d3 = 0.f;
                float d4 = 0.f, d5 = 0.f, d6 = 0.f, d7 = 0.f;
                #pragma unroll
                for (int n0 = 0; n0 < 1024; n0 += 256) {
                    d0 = fmaf(row[n0 + l],        cs[n0 + l],        d0);
                    d1 = fmaf(row[n0 + l + 32],   cs[n0 + l + 32],   d1);
                    d2 = fmaf(row[n0 + l + 64],   cs[n0 + l + 64],   d2);
                    d3 = fmaf(row[n0 + l + 96],   cs[n0 + l + 96],   d3);
                    d4 = fmaf(row[n0 + l + 128],  cs[n0 + l + 128],  d4);
                    d5 = fmaf(row[n0 + l + 160],  cs[n0 + l + 160],  d5);
                    d6 = fmaf(row[n0 + l + 192],  cs[n0 + l + 192],  d6);
                    d7 = fmaf(row[n0 + l + 224],  cs[n0 + l + 224],  d7);
                }
                float d = warpSum((((d0 + d1) + (d2 + d3)) + ((d4 + d5) + (d6 + d7))));
                if (l == 0) rs[k] = (1.0f / 65.0f) / d;
            }
            __syncthreads();
        }
    }
    g_c[b * 1024 + t] = cs[t];
    if (t < 65) g_r[b * 65 + t] = rs[t];
}

// ---------------------------------------------------------------------------
// GEMM C: partial (64x128) = p_slice @ f_slice, p materialized as K~ * r * c.
// ---------------------------------------------------------------------------
__global__ __launch_bounds__(256) void gemmC()
{
    const int b = blockIdx.y, sp = blockIdx.x;
    const int tid = threadIdx.x;
    const int tx = tid & 15, ty = tid >> 4;
    __shared__ float ps[64][33];
    __shared__ float fs[32][128];

    const int n0 = sp * 128;
    float acc[4][8];
    #pragma unroll
    for (int i = 0; i < 4; i++)
        #pragma unroll
        for (int j = 0; j < 8; j++) acc[i][j] = 0.0f;
    float psum = 0.0f;

    for (int c0 = 0; c0 < 128; c0 += 32) {
        __syncthreads();
        #pragma unroll
        for (int j = 0; j < 2; j++) {
            int idx4 = tid + j * 256;
            int k = idx4 >> 3;
            int nn4 = (idx4 & 7) * 4;
            float4 kv = *(const float4*)(g_K + ((size_t)(b * 64 + k)) * 1024 + n0 + c0 + nn4);
            float4 cv = *(const float4*)(g_c + b * 1024 + n0 + c0 + nn4);
            float rv = __ldg(&g_r[b * 65 + k]);
            ps[k][nn4 + 0] = kv.x * cv.x * rv;
            ps[k][nn4 + 1] = kv.y * cv.y * rv;
            ps[k][nn4 + 2] = kv.z * cv.z * rv;
            ps[k][nn4 + 3] = kv.w * cv.w * rv;
        }
        #pragma unroll
        for (int j = 0; j < 4; j++) {
            int idx4 = tid + j * 256;
            int nn = idx4 >> 5;
            int c4 = (idx4 & 31) * 4;
            *(float4*)&fs[nn][c4] =
                *(const float4*)(g_f + ((size_t)(b * 1024 + n0 + c0 + nn)) * 128 + c4);
        }
        __syncthreads();

        #pragma unroll
        for (int nn = 0; nn < 32; nn++) {
            float a4[4];
            #pragma unroll
            for (int i = 0; i < 4; i++) a4[i] = ps[ty * 4 + i][nn];
            float4 b0 = *(const float4*)&fs[nn][tx * 8];
            float4 b1 = *(const float4*)&fs[nn][tx * 8 + 4];
            float b8[8] = {b0.x, b0.y, b0.z, b0.w, b1.x, b1.y, b1.z, b1.w};
            #pragma unroll
            for (int i = 0; i < 4; i++)
                #pragma unroll
                for (int j = 0; j < 8; j++)
                    acc[i][j] = fmaf(a4[i], b8[j], acc[i][j]);
        }

        if (tid < 64) {
            float s = 0.0f;
            #pragma unroll
            for (int nn = 0; nn < 32; nn++) s += ps[tid][nn];
            psum += s;
        }
    }

    #pragma unroll
    for (int i = 0; i < 4; i++) {
        float* dst = g_vpart + (((size_t)(b * 8 + sp) * 64) + ty * 4 + i) * 128 + tx * 8;
        *(float4*)(dst)     = make_float4(acc[i][0], acc[i][1], acc[i][2], acc[i][3]);
        *(float4*)(dst + 4) = make_float4(acc[i][4], acc[i][5], acc[i][6], acc[i][7]);
    }
    if (tid < 64) g_pspart[(b * 8 + sp) * 64 + tid] = psum;
}

// ----- finalK: split-K reduce + anchors + t concat + L2 normalize ------------
__global__ __launch_bounds__(1024) void finalK(
    const float* __restrict__ anchors, float* __restrict__ out)
{
    const int b = blockIdx.x, t = threadIdx.x;
    float* orow = out + (size_t)b * 8448;
    float ss = 0.0f;

    #pragma unroll
    for (int j = 0; j < 8; j++) {
        int e = t + j * 1024;
        int k = e >> 7, c = e & 127;
        float s2 = 0.0f, sps = 0.0f;
        #pragma unroll
        for (int sp = 0; sp < 8; sp++) {
            s2  += g_vpart[(((size_t)(b * 8 + sp) * 64) + k) * 128 + c];
            sps += g_pspart[(b * 8 + sp) * 64 + k];
        }
        float val = 2.0f * s2 - sps * anchors[k * 128 + c];
        orow[256 + e] = val;
        ss += val * val;
    }
    if (t < 256) {
        float tv = g_t[b * 256 + t];
        orow[t] = tv;
        ss += tv * tv;
    }

    __shared__ float red[32];
    __shared__ float s_inv;
    float w = warpSum(ss);
    if ((t & 31) == 0) red[t >> 5] = w;
    __syncthreads();
    if (t < 32) {
        float v = red[t];
        v = warpSum(v);
        if (t == 0) s_inv = 1.0f / fmaxf(sqrtf(v), 1e-12f);
    }
    __syncthreads();
    const float inv = s_inv;
    for (int idx = t; idx < 8448; idx += 1024) orow[idx] *= inv;
}

// ---------------------------------------------------------------------------
extern "C" void kernel_launch(void* const* d_in, const int* in_sizes, int n_in,
                              void* d_out, int out_size)
{
    const float* x       = (const float*)d_in[0];
    const float* Wf      = (const float*)d_in[1];
    const float* bf      = (const float*)d_in[2];
    const float* Ws      = (const float*)d_in[3];
    const float* bs      = (const float*)d_in[4];
    const float* Wt      = (const float*)d_in[5];
    const float* bt      = (const float*)d_in[6];
    const float* anchors = (const float*)d_in[7];
    // d_in[8] = dust_bin: constant row shift, cancels in the transport plan.
    const float* sharp   = (const float*)d_in[9];
    float* out = (float*)d_out;

    static int smem_set = 0;
    if (!smem_set) {
        cudaFuncSetAttribute(gemmA_mma, cudaFuncAttributeMaxDynamicSharedMemorySize, SM_TOTAL);
        smem_set = 1;
    }

    prepBf<<<384, 256>>>(Wf);                       // launch 0
    prepBs<<<192, 256>>>(Ws);                       // launch 1
    tG<<<32, 256>>>(x, Wt, bt);                     // launch 2
    gemmA_mma<<<dim3(8, 32), 512, SM_TOTAL>>>(x, bf, bs, sharp);  // launch 3 (ncu slot)
    expprep<<<2048, 256>>>();
    sinkhorn<<<32, 1024>>>();
    gemmC<<<dim3(8, 32), 256>>>();
    finalK<<<32, 1024>>>(anchors, out);
}

// round 10
// speedup vs baseline: 1.2412x; 1.0582x over previous
#include <cuda_runtime.h>
#include <cuda_fp16.h>
#include <math.h>
#include <stdint.h>

#define LOG2E_F 1.4426950408889634f

// ---------------- scratch (static device globals; no allocs) ----------------
__device__ float  g_K[32 * 64 * 1024];        // M' -> K~ (in place)       8 MB
__device__ float  g_r[32 * 65];               // Sinkhorn row scalings
__device__ float  g_c[32 * 1024];             // Sinkhorn col scalings
__device__ float  g_vpart[32 * 8 * 64 * 128]; // split-K partials of p@f
__device__ float  g_pspart[32 * 8 * 64];      // split-K partials of rowsum(p)
__device__ float  g_t[32 * 256];              // t = x0 @ Wt + bt
__device__ __half g_Bhi[192 * 768];           // (W^T * 256) hi, [n][k]
__device__ __half g_Blo[192 * 768];           // (W^T * 256) lo
__device__ __half g_fh[32 * 1024 * 128];      // f hi (half)              8 MB
__device__ __half g_fl[32 * 1024 * 128];      // f lo (half)              8 MB

// ------------------------------- helpers -------------------------------------
__device__ __forceinline__ float warpSum(float v) {
    #pragma unroll
    for (int o = 16; o > 0; o >>= 1) v += __shfl_xor_sync(0xffffffffu, v, o);
    return v;
}
__device__ __forceinline__ float warpMax(float v) {
    #pragma unroll
    for (int o = 16; o > 0; o >>= 1) v = fmaxf(v, __shfl_xor_sync(0xffffffffu, v, o));
    return v;
}
// exp2 on the FMA pipe (x <= 0 here). deg-5 Taylor, rel err ~2e-6.
__device__ __forceinline__ float exp2_fma(float x) {
    x = fmaxf(x, -125.0f);
    int   ni = __float2int_rn(x);
    float f  = x - (float)ni;
    float p  = 1.3333558e-3f;
    p = fmaf(p, f, 9.6181290e-3f);
    p = fmaf(p, f, 5.5504109e-2f);
    p = fmaf(p, f, 2.4022651e-1f);
    p = fmaf(p, f, 6.9314718e-1f);
    p = fmaf(p, f, 1.0f);
    return p * __int_as_float((ni + 127) << 23);
}
__device__ __forceinline__ void mma16816(float* d, uint32_t a0, uint32_t a1,
                                         uint32_t a2, uint32_t a3,
                                         uint32_t b0, uint32_t b1) {
    asm volatile(
        "mma.sync.aligned.m16n8k16.row.col.f32.f16.f16.f32 "
        "{%0,%1,%2,%3}, {%4,%5,%6,%7}, {%8,%9}, {%0,%1,%2,%3};"
        : "+f"(d[0]), "+f"(d[1]), "+f"(d[2]), "+f"(d[3])
        : "r"(a0), "r"(a1), "r"(a2), "r"(a3), "r"(b0), "r"(b1));
}
__device__ __forceinline__ void ldsm4(uint32_t& r0, uint32_t& r1,
                                      uint32_t& r2, uint32_t& r3, uint32_t a) {
    asm volatile("ldmatrix.sync.aligned.m8n8.x4.shared.b16 {%0,%1,%2,%3}, [%4];"
                 : "=r"(r0), "=r"(r1), "=r"(r2), "=r"(r3) : "r"(a));
}
__device__ __forceinline__ void ldsm4t(uint32_t& r0, uint32_t& r1,
                                       uint32_t& r2, uint32_t& r3, uint32_t a) {
    asm volatile("ldmatrix.sync.aligned.m8n8.x4.trans.shared.b16 {%0,%1,%2,%3}, [%4];"
                 : "=r"(r0), "=r"(r1), "=r"(r2), "=r"(r3) : "r"(a));
}
__device__ __forceinline__ uint32_t pack_h2(__half a, __half b) {
    __half2 h = __halves2half2(a, b);
    return *(uint32_t*)&h;
}
__device__ __forceinline__ uint32_t smem_u32(const void* p) {
    uint32_t a;
    asm("{ .reg .u64 t; cvta.to.shared.u64 t, %1; cvt.u32.u64 %0, t; }" : "=r"(a) : "l"(p));
    return a;
}
__device__ __forceinline__ void cpasync16(uint32_t dst, const void* src) {
    asm volatile("cp.async.cg.shared.global [%0], [%1], 16;" :: "r"(dst), "l"(src));
}
#define CP_COMMIT() asm volatile("cp.async.commit_group;" ::: "memory")
#define CP_WAIT0()  asm volatile("cp.async.wait_group 0;" ::: "memory")

// ------------------- prepB (split in two for launch-slot layout) -------------
__global__ __launch_bounds__(256) void prepBf(const float* __restrict__ Wf)
{
    int i = blockIdx.x * 256 + threadIdx.x;     // 128*768
    int n = i / 768, k = i - n * 768;
    float v = Wf[(size_t)k * 128 + n] * 256.0f;
    __half hi = __float2half_rn(v);
    g_Bhi[i] = hi;
    g_Blo[i] = __float2half_rn(v - __half2float(hi));
}
__global__ __launch_bounds__(256) void prepBs(const float* __restrict__ Ws)
{
    int i = blockIdx.x * 256 + threadIdx.x;     // 64*768
    int n = i / 768, k = i - n * 768;
    float v = Ws[(size_t)k * 64 + n] * 256.0f;
    __half hi = __float2half_rn(v);
    g_Bhi[128 * 768 + i] = hi;
    g_Blo[128 * 768 + i] = __float2half_rn(v - __half2float(hi));
}

// --------------------------- tG: t = x[:,0] @ Wt + bt ------------------------
__global__ __launch_bounds__(256) void tG(
    const float* __restrict__ x, const float* __restrict__ Wt,
    const float* __restrict__ bt)
{
    const int b = blockIdx.x;
    const int c = threadIdx.x;
    __shared__ float xs[768];
    for (int i = c; i < 768; i += 256) xs[i] = x[(size_t)b * 1025 * 768 + i];
    __syncthreads();
    float acc = bt[c];
    #pragma unroll 8
    for (int d = 0; d < 768; d++) acc = fmaf(xs[d], Wt[(size_t)d * 256 + c], acc);
    g_t[b * 256 + c] = acc;
}

// ---------------------------------------------------------------------------
// gemmA via mma.sync + ldmatrix, double-buffered A and B smem.
// f cols: 1-term; s cols: 3-term. f written as half hi/lo for gemmC.
// ---------------------------------------------------------------------------
#define A_MAT  18432                          // 128 rows * 144 B
#define SMA_HI(buf) ((buf) * (2 * A_MAT))
#define SMA_LO_OFF A_MAT
#define B_HI_SZ 27648                         // 192 * 144
#define B_LOS_SZ 9216                         // 64 * 144
#define B_BUF (B_HI_SZ + B_LOS_SZ)            // 36864
#define SMB_HI(buf) (4 * A_MAT + (buf) * B_BUF)
#define SMB_LOS_OFF B_HI_SZ
#define SM_TOTAL (4 * A_MAT + 2 * B_BUF)      // 147456 B

__global__ __launch_bounds__(512) void gemmA_mma(
    const float* __restrict__ x, const float* __restrict__ bf,
    const float* __restrict__ bs, const float* __restrict__ sharp)
{
    extern __shared__ char sm[];
    const uint32_t smu = smem_u32(sm);
    const int tid = threadIdx.x, wid = tid >> 5, lane = tid & 31;
    const int b = blockIdx.y, nt = blockIdx.x;
    const int wr = wid & 3, wc = wid >> 2;          // 4 x 4 warp grid
    const int g = lane >> 2, tig = lane & 3;

    const int rl = lane & 15, kh = lane >> 4;
    const uint32_t aOff   = (uint32_t)((wr * 32 + rl) * 144 + kh * 16);
    const uint32_t bfOff  = (uint32_t)((wc * 32 + rl) * 144 + kh * 16);
    const uint32_t bshOff = (uint32_t)((128 + wc * 16 + rl) * 144 + kh * 16);
    const uint32_t bslOff = (uint32_t)(SMB_LOS_OFF + (wc * 16 + rl) * 144 + kh * 16);

    const float* A = x + (size_t)b * 1025 * 768 + 768 + (size_t)nt * 128 * 768;
    const int am = tid >> 2, akb = (tid & 3) * 16;
    const float* aptr = A + (size_t)am * 768 + akb;
    const uint32_t cvtOff = (uint32_t)(am * 144 + akb * 2);

    float acc[2][6][4];
    float accS2[2][2][4];
    #pragma unroll
    for (int mf = 0; mf < 2; mf++) {
        #pragma unroll
        for (int nf = 0; nf < 6; nf++)
            #pragma unroll
            for (int q = 0; q < 4; q++) acc[mf][nf][q] = 0.0f;
        #pragma unroll
        for (int nf = 0; nf < 2; nf++)
            #pragma unroll
            for (int q = 0; q < 4; q++) accS2[mf][nf][q] = 0.0f;
    }

    float4 aPre[4];

    #define CONVERT_A(WBUF)                                                     \
    do {                                                                        \
        char* dhi = sm + SMA_HI(WBUF) + cvtOff;                                 \
        uint32_t hq[4], lq[4];                                                  \
        _Pragma("unroll")                                                       \
        for (int i = 0; i < 4; i++) {                                           \
            float4 v = aPre[i];                                                 \
            __half hx = __float2half_rn(v.x), hy = __float2half_rn(v.y);        \
            __half hz = __float2half_rn(v.z), hw = __float2half_rn(v.w);        \
            __half lx = __float2half_rn(v.x - __half2float(hx));                \
            __half ly = __float2half_rn(v.y - __half2float(hy));                \
            __half lz = __float2half_rn(v.z - __half2float(hz));                \
            __half lw = __float2half_rn(v.w - __half2float(hw));                \
            hq[i] = 0; lq[i] = 0;                                               \
            hq[i] = pack_h2(hx, hy); lq[i] = pack_h2(lx, ly);                   \
            uint32_t hq2 = pack_h2(hz, hw), lq2 = pack_h2(lz, lw);              \
            if (i == 0) { h0 = make_uint4(hq[0], hq2, 0, 0); l0 = make_uint4(lq[0], lq2, 0, 0); } \
            else if (i == 1) { h0.z = hq[1]; h0.w = hq2; l0.z = lq[1]; l0.w = lq2; } \
            else if (i == 2) { h1 = make_uint4(hq[2], hq2, 0, 0); l1 = make_uint4(lq[2], lq2, 0, 0); } \
            else { h1.z = hq[3]; h1.w = hq2; l1.z = lq[3]; l1.w = lq2; }        \
        }                                                                       \
        *(uint4*)(dhi) = h0;  *(uint4*)(dhi + 16) = h1;                         \
        *(uint4*)(dhi + SMA_LO_OFF) = l0; *(uint4*)(dhi + SMA_LO_OFF + 16) = l1;\
    } while (0)

    #define FETCH_B(CH, WBUF)                                                   \
    do {                                                                        \
        const int kk0 = (CH) * 64;                                              \
        _Pragma("unroll")                                                       \
        for (int j = 0; j < 3; j++) {                                           \
            int e = tid + j * 512;                                              \
            int n = e >> 3, u = e & 7;                                          \
            cpasync16(smu + SMB_HI(WBUF) + (uint32_t)(n * 144 + u * 16),        \
                      g_Bhi + (size_t)n * 768 + kk0 + u * 8);                   \
        }                                                                       \
        {                                                                       \
            int n = tid >> 3, u = tid & 7;                                      \
            if (n < 64)                                                         \
                cpasync16(smu + SMB_HI(WBUF) + SMB_LOS_OFF +                    \
                          (uint32_t)(n * 144 + u * 16),                         \
                          g_Blo + (size_t)(128 + n) * 768 + kk0 + u * 8);       \
        }                                                                       \
        CP_COMMIT();                                                            \
    } while (0)

    uint4 h0, h1, l0, l1;

    // ---- prologue ----
    #pragma unroll
    for (int i = 0; i < 4; i++) aPre[i] = *(const float4*)(aptr + i * 4);
    FETCH_B(0, 0);
    CONVERT_A(0);
    #pragma unroll
    for (int i = 0; i < 4; i++) aPre[i] = *(const float4*)(aptr + 64 + i * 4);
    CP_WAIT0();
    __syncthreads();

    #pragma unroll 1
    for (int ch = 0; ch < 12; ch++) {
        const int buf = ch & 1;
        if (ch < 11) {
            FETCH_B(ch + 1, buf ^ 1);
            CONVERT_A(buf ^ 1);
            if (ch < 10) {
                const int k2 = (ch + 2) * 64;
                #pragma unroll
                for (int i = 0; i < 4; i++) aPre[i] = *(const float4*)(aptr + k2 + i * 4);
            }
        }

        const uint32_t aHiB = smu + SMA_HI(buf) + aOff;
        const uint32_t aLoB = aHiB + SMA_LO_OFF;
        const uint32_t bHfB = smu + SMB_HI(buf) + bfOff;
        const uint32_t bHsB = smu + SMB_HI(buf) + bshOff;
        const uint32_t bLsB = smu + SMB_HI(buf) + bslOff;
        #pragma unroll
        for (int ks = 0; ks < 4; ks++) {
            const uint32_t ko = ks * 32;
            uint32_t ah[2][4], al[2][4];
            uint32_t bsh0, bsh1, bsh2, bsh3, bsl0, bsl1, bsl2, bsl3;
            uint32_t bfa[4], bfb[4];
            ldsm4(ah[0][0], ah[0][1], ah[0][2], ah[0][3], aHiB + ko);
            ldsm4(ah[1][0], ah[1][1], ah[1][2], ah[1][3], aHiB + 16 * 144 + ko);
            ldsm4(bsh0, bsh1, bsh2, bsh3, bHsB + ko);
            ldsm4(al[0][0], al[0][1], al[0][2], al[0][3], aLoB + ko);
            ldsm4(al[1][0], al[1][1], al[1][2], al[1][3], aLoB + 16 * 144 + ko);
            ldsm4(bsl0, bsl1, bsl2, bsl3, bLsB + ko);
            ldsm4(bfa[0], bfa[1], bfa[2], bfa[3], bHfB + ko);
            ldsm4(bfb[0], bfb[1], bfb[2], bfb[3], bHfB + 16 * 144 + ko);

            mma16816(acc[0][4], ah[0][0], ah[0][1], ah[0][2], ah[0][3], bsh0, bsh2);
            mma16816(acc[0][5], ah[0][0], ah[0][1], ah[0][2], ah[0][3], bsh1, bsh3);
            mma16816(acc[1][4], ah[1][0], ah[1][1], ah[1][2], ah[1][3], bsh0, bsh2);
            mma16816(acc[1][5], ah[1][0], ah[1][1], ah[1][2], ah[1][3], bsh1, bsh3);
            mma16816(acc[0][0], ah[0][0], ah[0][1], ah[0][2], ah[0][3], bfa[0], bfa[2]);
            mma16816(acc[0][1], ah[0][0], ah[0][1], ah[0][2], ah[0][3], bfa[1], bfa[3]);
            mma16816(acc[1][0], ah[1][0], ah[1][1], ah[1][2], ah[1][3], bfa[0], bfa[2]);
            mma16816(acc[1][1], ah[1][0], ah[1][1], ah[1][2], ah[1][3], bfa[1], bfa[3]);
            mma16816(accS2[0][0], ah[0][0], ah[0][1], ah[0][2], ah[0][3], bsl0, bsl2);
            mma16816(accS2[0][1], ah[0][0], ah[0][1], ah[0][2], ah[0][3], bsl1, bsl3);
            mma16816(accS2[1][0], ah[1][0], ah[1][1], ah[1][2], ah[1][3], bsl0, bsl2);
            mma16816(accS2[1][1], ah[1][0], ah[1][1], ah[1][2], ah[1][3], bsl1, bsl3);
            mma16816(acc[0][2], ah[0][0], ah[0][1], ah[0][2], ah[0][3], bfb[0], bfb[2]);
            mma16816(acc[0][3], ah[0][0], ah[0][1], ah[0][2], ah[0][3], bfb[1], bfb[3]);
            mma16816(acc[1][2], ah[1][0], ah[1][1], ah[1][2], ah[1][3], bfb[0], bfb[2]);
            mma16816(acc[1][3], ah[1][0], ah[1][1], ah[1][2], ah[1][3], bfb[1], bfb[3]);
            mma16816(acc[0][4], al[0][0], al[0][1], al[0][2], al[0][3], bsh0, bsh2);
            mma16816(acc[0][5], al[0][0], al[0][1], al[0][2], al[0][3], bsh1, bsh3);
            mma16816(acc[1][4], al[1][0], al[1][1], al[1][2], al[1][3], bsh0, bsh2);
            mma16816(acc[1][5], al[1][0], al[1][1], al[1][2], al[1][3], bsh1, bsh3);
        }
        if (ch < 11) CP_WAIT0();
        __syncthreads();
    }

    // ---------------------------- epilogue ----------------------------------
    const float inv256 = 1.0f / 256.0f;
    const float scl = sharp[0] * 10.0f * LOG2E_F;
    #pragma unroll
    for (int mf = 0; mf < 2; mf++) {
        #pragma unroll
        for (int nf = 0; nf < 4; nf++) {
            int c = wc * 32 + nf * 8 + tig * 2;
            int r0 = nt * 128 + wr * 32 + mf * 16 + g;
            int r1 = r0 + 8;
            float b0 = __ldg(bf + c), b1 = __ldg(bf + c + 1);
            float f00 = fmaf(acc[mf][nf][0], inv256, b0);
            float f01 = fmaf(acc[mf][nf][1], inv256, b1);
            float f10 = fmaf(acc[mf][nf][2], inv256, b0);
            float f11 = fmaf(acc[mf][nf][3], inv256, b1);
            __half h00 = __float2half_rn(f00), h01 = __float2half_rn(f01);
            __half h10 = __float2half_rn(f10), h11 = __float2half_rn(f11);
            size_t i0 = ((size_t)(b * 1024 + r0)) * 128 + c;
            size_t i1 = ((size_t)(b * 1024 + r1)) * 128 + c;
            *(uint32_t*)(g_fh + i0) = pack_h2(h00, h01);
            *(uint32_t*)(g_fh + i1) = pack_h2(h10, h11);
            *(uint32_t*)(g_fl + i0) = pack_h2(__float2half_rn(f00 - __half2float(h00)),
                                              __float2half_rn(f01 - __half2float(h01)));
            *(uint32_t*)(g_fl + i1) = pack_h2(__float2half_rn(f10 - __half2float(h10)),
                                              __float2half_rn(f11 - __half2float(h11)));
        }
        #pragma unroll
        for (int nf = 4; nf < 6; nf++) {
            int k = wc * 16 + (nf - 4) * 8 + tig * 2;
            int r0 = nt * 128 + wr * 32 + mf * 16 + g;
            int r1 = r0 + 8;
            float b0 = __ldg(bs + k), b1 = __ldg(bs + k + 1);
            float* K0 = g_K + ((size_t)(b * 64 + k)) * 1024;
            float* K1 = g_K + ((size_t)(b * 64 + k + 1)) * 1024;
            float d0 = acc[mf][nf][0] + accS2[mf][nf - 4][0];
            float d1 = acc[mf][nf][1] + accS2[mf][nf - 4][1];
            float d2 = acc[mf][nf][2] + accS2[mf][nf - 4][2];
            float d3 = acc[mf][nf][3] + accS2[mf][nf - 4][3];
            K0[r0] = fmaf(d0, inv256, b0) * scl;
            K1[r0] = fmaf(d1, inv256, b1) * scl;
            K0[r1] = fmaf(d2, inv256, b0) * scl;
            K1[r1] = fmaf(d3, inv256, b1) * scl;
        }
    }
}

// ------ sinkhorn (fused expprep phase + 5 c-updates + 4 r-updates) -----------
__global__ __launch_bounds__(1024) void sinkhorn()
{
    const int b = blockIdx.x;
    const int t = threadIdx.x, w = t >> 5, l = t & 31;
    __shared__ float cs[1024];
    __shared__ float rs[72];
    __shared__ float red[32];
    float* Kb = g_K + ((size_t)b << 16);

    // ---- phase 1: rowmax + exp2 + rowsum (warp w -> rows w, w+32) ----
    #pragma unroll
    for (int rr = 0; rr < 2; rr++) {
        int k = w + rr * 32;
        float* row = Kb + ((size_t)k << 10);
        float m = -INFINITY;
        #pragma unroll 8
        for (int n = l; n < 1024; n += 32) m = fmaxf(m, row[n]);
        m = warpMax(m);
        float s = 0.0f;
        #pragma unroll 8
        for (int n = l; n < 1024; n += 32) {
            float e = exp2_fma(row[n] - m);
            row[n] = e;
            s += e;
        }
        s = warpSum(s);
        if (l == 0) rs[k] = (1.0f / 65.0f) / s;
    }
    if (t == 0) rs[64] = (1.0f / 65.0f) / 1024.0f;
    __syncthreads();

    // ---- iterations ----
    #pragma unroll 1
    for (int it = 0; it < 5; it++) {
        const float* col = Kb + t;
        float a0 = rs[64], a1 = 0.f, a2 = 0.f, a3 = 0.f;
        float a4 = 0.f, a5 = 0.f, a6 = 0.f, a7 = 0.f;
        #pragma unroll
        for (int k = 0; k < 64; k += 8) {
            a0 = fmaf(col[(size_t)(k + 0) << 10], rs[k + 0], a0);
            a1 = fmaf(col[(size_t)(k + 1) << 10], rs[k + 1], a1);
            a2 = fmaf(col[(size_t)(k + 2) << 10], rs[k + 2], a2);
            a3 = fmaf(col[(size_t)(k + 3) << 10], rs[k + 3], a3);
            a4 = fmaf(col[(size_t)(k + 4) << 10], rs[k + 4], a4);
            a5 = fmaf(col[(size_t)(k + 5) << 10], rs[k + 5], a5);
            a6 = fmaf(col[(size_t)(k + 6) << 10], rs[k + 6], a6);
            a7 = fmaf(col[(size_t)(k + 7) << 10], rs[k + 7], a7);
        }
        float cv = (1.0f / 1024.0f) /
                   (((a0 + a1) + (a2 + a3)) + ((a4 + a5) + (a6 + a7)));
        cs[t] = cv;
        float sw = warpSum(cv);
        if (l == 0) red[w] = sw;
        __syncthreads();
        if (it < 4) {
            if (t == 0) {
                float s = 0.0f;
                #pragma unroll
                for (int i = 0; i < 32; i++) s += red[i];
                rs[64] = (1.0f / 65.0f) / s;
            }
            #pragma unroll
            for (int rr = 0; rr < 2; rr++) {
                int k = w + rr * 32;
                const float* row = Kb + ((size_t)k << 10);
                float d0 = 0.f, d1 = 0.f, d2 = 0.f, d3 = 0.f;
                float d4 = 0.f, d5 = 0.f, d6 = 0.f, d7 = 0.f;
                #pragma unroll
                for (int n0 = 0; n0 < 1024; n0 += 256) {
                    d0 = fmaf(row[n0 + l],        cs[n0 + l],        d0);
                    d1 = fmaf(row[n0 + l + 32],   cs[n0 + l + 32],   d1);
                    d2 = fmaf(row[n0 + l + 64],   cs[n0 + l + 64],   d2);
                    d3 = fmaf(row[n0 + l + 96],   cs[n0 + l + 96],   d3);
                    d4 = fmaf(row[n0 + l + 128],  cs[n0 + l + 128],  d4);
                    d5 = fmaf(row[n0 + l + 160],  cs[n0 + l + 160],  d5);
                    d6 = fmaf(row[n0 + l + 192],  cs[n0 + l + 192],  d6);
                    d7 = fmaf(row[n0 + l + 224],  cs[n0 + l + 224],  d7);
                }
                float d = warpSum((((d0 + d1) + (d2 + d3)) + ((d4 + d5) + (d6 + d7))));
                if (l == 0) rs[k] = (1.0f / 65.0f) / d;
            }
            __syncthreads();
        }
    }
    g_c[b * 1024 + t] = cs[t];
    if (t < 65) g_r[b * 65 + t] = rs[t];
}

// ---------------------------------------------------------------------------
// gemmC via mma.sync: partial (64x128) = p_slice @ f_slice over 128 n.
// p built on the fly (K~ r c), scaled x256, fp16 hi/lo; f preconverted hi/lo.
// Terms: ph*fh + ph*fl + pl*fh.
// ---------------------------------------------------------------------------
#define PSH_HI 0
#define PSH_LO 17408
#define FSH_HI 34816
#define FSH_LO 69632
#define SMC_TOTAL 104448

__global__ __launch_bounds__(256) void gemmC_mma()
{
    extern __shared__ char sm[];
    const uint32_t smu = smem_u32(sm);
    const int b = blockIdx.y, sp = blockIdx.x;
    const int tid = threadIdx.x, wid = tid >> 5, lane = tid & 31;
    const int wr = wid & 1, wc = wid >> 1;          // 2 x 4 warp grid
    const int g = lane >> 2, tig = lane & 3;
    const int rl = lane & 15, kh = lane >> 4;
    const int n0 = sp * 128;

    // ---- fill f tiles via cp.async ----
    #pragma unroll
    for (int j = 0; j < 8; j++) {
        int e = tid + j * 256;
        int n = e >> 4, u = e & 15;
        uint32_t doff = (uint32_t)(n * 272 + u * 16);
        size_t src = ((size_t)(b * 1024 + n0 + n)) * 128 + u * 8;
        cpasync16(smu + FSH_HI + doff, g_fh + src);
        cpasync16(smu + FSH_LO + doff, g_fl + src);
    }
    CP_COMMIT();

    // ---- build p (scaled x256) into smem hi/lo + rowsum ----
    {
        const int k = tid >> 2, nq = (tid & 3) * 32;
        const float rv = __ldg(&g_r[b * 65 + k]) * 256.0f;
        const float4* Kp = (const float4*)(g_K + ((size_t)(b * 64 + k)) * 1024 + n0 + nq);
        const float4* Cp = (const float4*)(g_c + b * 1024 + n0 + nq);
        char* ph = sm + PSH_HI + (k * 136 + nq) * 2;
        char* pl = sm + PSH_LO + (k * 136 + nq) * 2;
        float psum = 0.0f;
        #pragma unroll
        for (int j = 0; j < 8; j++) {
            float4 kv = Kp[j];
            float4 cv = Cp[j];
            float p0 = kv.x * cv.x * rv, p1 = kv.y * cv.y * rv;
            float p2 = kv.z * cv.z * rv, p3 = kv.w * cv.w * rv;
            psum += (p0 + p1) + (p2 + p3);
            __half h0 = __float2half_rn(p0), h1 = __float2half_rn(p1);
            __half h2 = __float2half_rn(p2), h3 = __float2half_rn(p3);
            *(uint2*)(ph + j * 8) = make_uint2(pack_h2(h0, h1), pack_h2(h2, h3));
            *(uint2*)(pl + j * 8) = make_uint2(
                pack_h2(__float2half_rn(p0 - __half2float(h0)),
                        __float2half_rn(p1 - __half2float(h1))),
                pack_h2(__float2half_rn(p2 - __half2float(h2)),
                        __float2half_rn(p3 - __half2float(h3))));
        }
        psum += __shfl_xor_sync(0xffffffffu, psum, 1);
        psum += __shfl_xor_sync(0xffffffffu, psum, 2);
        if ((tid & 3) == 0)
            g_pspart[(b * 8 + sp) * 64 + k] = psum * (1.0f / 256.0f);
    }
    CP_WAIT0();
    __syncthreads();

    // ---- MMA: M=64 (k), N=128 (c), K=128 (n) ----
    float acc[2][4][4];
    #pragma unroll
    for (int mf = 0; mf < 2; mf++)
        #pragma unroll
        for (int nf = 0; nf < 4; nf++)
            #pragma unroll
            for (int q = 0; q < 4; q++) acc[mf][nf][q] = 0.0f;

    const uint32_t pHiB = smu + PSH_HI + (wr * 32 + rl) * 272 + kh * 16;
    const uint32_t pLoB = pHiB + (PSH_LO - PSH_HI);
    // f B-operand via ldsm4.trans: lanes 0-15 -> n-rows, lanes 16-31 -> +8 cols
    const uint32_t fHiB = smu + FSH_HI + rl * 272 + (wc * 32) * 2 + kh * 16;
    const uint32_t fLoB = fHiB + (FSH_LO - FSH_HI);

    #pragma unroll
    for (int s = 0; s < 8; s++) {
        const uint32_t ko = s * 32;            // A k-offset bytes (16 halfs)
        const uint32_t fo = s * 16 * 272;      // B n-row offset bytes
        uint32_t ph[2][4], pl[2][4];
        uint32_t bh0[4], bh1[4], bl0[4], bl1[4];
        ldsm4(ph[0][0], ph[0][1], ph[0][2], ph[0][3], pHiB + ko);
        ldsm4(ph[1][0], ph[1][1], ph[1][2], ph[1][3], pHiB + 16 * 272 + ko);
        ldsm4(pl[0][0], pl[0][1], pl[0][2], pl[0][3], pLoB + ko);
        ldsm4(pl[1][0], pl[1][1], pl[1][2], pl[1][3], pLoB + 16 * 272 + ko);
        ldsm4t(bh0[0], bh0[1], bh0[2], bh0[3], fHiB + fo);
        ldsm4t(bh1[0], bh1[1], bh1[2], bh1[3], fHiB + fo + 32);
        ldsm4t(bl0[0], bl0[1], bl0[2], bl0[3], fLoB + fo);
        ldsm4t(bl1[0], bl1[1], bl1[2], bl1[3], fLoB + fo + 32);

        #pragma unroll
        for (int mf = 0; mf < 2; mf++) {
            // term 1: ph * fh
            mma16816(acc[mf][0], ph[mf][0], ph[mf][1], ph[mf][2], ph[mf][3], bh0[0], bh0[1]);
            mma16816(acc[mf][1], ph[mf][0], ph[mf][1], ph[mf][2], ph[mf][3], bh0[2], bh0[3]);
            mma16816(acc[mf][2], ph[mf][0], ph[mf][1], ph[mf][2], ph[mf][3], bh1[0], bh1[1]);
            mma16816(acc[mf][3], ph[mf][0], ph[mf][1], ph[mf][2], ph[mf][3], bh1[2], bh1[3]);
            // term 2: ph * fl
            mma16816(acc[mf][0], ph[mf][0], ph[mf][1], ph[mf][2], ph[mf][3], bl0[0], bl0[1]);
            mma16816(acc[mf][1], ph[mf][0], ph[mf][1], ph[mf][2], ph[mf][3], bl0[2], bl0[3]);
            mma16816(acc[mf][2], ph[mf][0], ph[mf][1], ph[mf][2], ph[mf][3], bl1[0], bl1[1]);
            mma16816(acc[mf][3], ph[mf][0], ph[mf][1], ph[mf][2], ph[mf][3], bl1[2], bl1[3]);
            // term 3: pl * fh
            mma16816(acc[mf][0], pl[mf][0], pl[mf][1], pl[mf][2], pl[mf][3], bh0[0], bh0[1]);
            mma16816(acc[mf][1], pl[mf][0], pl[mf][1], pl[mf][2], pl[mf][3], bh0[2], bh0[3]);
            mma16816(acc[mf][2], pl[mf][0], pl[mf][1], pl[mf][2], pl[mf][3], bh1[0], bh1[1]);
            mma16816(acc[mf][3], pl[mf][0], pl[mf][1], pl[mf][2], pl[mf][3], bh1[2], bh1[3]);
        }
    }

    // ---- epilogue: vpart = acc / 256 ----
    const float inv256 = 1.0f / 256.0f;
    #pragma unroll
    for (int mf = 0; mf < 2; mf++) {
        #pragma unroll
        for (int nf = 0; nf < 4; nf++) {
            int k0 = wr * 32 + mf * 16 + g;
            int c = wc * 32 + nf * 8 + tig * 2;
            float* base = g_vpart + ((size_t)(b * 8 + sp) * 64) * 128;
            *(float2*)(base + (size_t)k0 * 128 + c) =
                make_float2(acc[mf][nf][0] * inv256, acc[mf][nf][1] * inv256);
            *(float2*)(base + (size_t)(k0 + 8) * 128 + c) =
                make_float2(acc[mf][nf][2] * inv256, acc[mf][nf][3] * inv256);
        }
    }
}

// ----- finalK: split-K reduce + anchors + t concat + L2 normalize ------------
__global__ __launch_bounds__(1024) void finalK(
    const float* __restrict__ anchors, float* __restrict__ out)
{
    const int b = blockIdx.x, t = threadIdx.x;
    float* orow = out + (size_t)b * 8448;
    float ss = 0.0f;

    #pragma unroll
    for (int j = 0; j < 8; j++) {
        int e = t + j * 1024;
        int k = e >> 7, c = e & 127;
        float s2 = 0.0f, sps = 0.0f;
        #pragma unroll
        for (int sp = 0; sp < 8; sp++) {
            s2  += g_vpart[(((size_t)(b * 8 + sp) * 64) + k) * 128 + c];
            sps += g_pspart[(b * 8 + sp) * 64 + k];
        }
        float val = 2.0f * s2 - sps * anchors[k * 128 + c];
        orow[256 + e] = val;
        ss += val * val;
    }
    if (t < 256) {
        float tv = g_t[b * 256 + t];
        orow[t] = tv;
        ss += tv * tv;
    }

    __shared__ float red[32];
    __shared__ float s_inv;
    float w = warpSum(ss);
    if ((t & 31) == 0) red[t >> 5] = w;
    __syncthreads();
    if (t < 32) {
        float v = red[t];
        v = warpSum(v);
        if (t == 0) s_inv = 1.0f / fmaxf(sqrtf(v), 1e-12f);
    }
    __syncthreads();
    const float inv = s_inv;
    for (int idx = t; idx < 8448; idx += 1024) orow[idx] *= inv;
}

// ---------------------------------------------------------------------------
extern "C" void kernel_launch(void* const* d_in, const int* in_sizes, int n_in,
                              void* d_out, int out_size)
{
    const float* x       = (const float*)d_in[0];
    const float* Wf      = (const float*)d_in[1];
    const float* bf      = (const float*)d_in[2];
    const float* Ws      = (const float*)d_in[3];
    const float* bs      = (const float*)d_in[4];
    const float* Wt      = (const float*)d_in[5];
    const float* bt      = (const float*)d_in[6];
    const float* anchors = (const float*)d_in[7];
    // d_in[8] = dust_bin: constant row shift, cancels in the transport plan.
    const float* sharp   = (const float*)d_in[9];
    float* out = (float*)d_out;

    static int smem_set = 0;
    if (!smem_set) {
        cudaFuncSetAttribute(gemmA_mma, cudaFuncAttributeMaxDynamicSharedMemorySize, SM_TOTAL);
        cudaFuncSetAttribute(gemmC_mma, cudaFuncAttributeMaxDynamicSharedMemorySize, SMC_TOTAL);
        smem_set = 1;
    }

    prepBf<<<384, 256>>>(Wf);                       // launch 0
    prepBs<<<192, 256>>>(Ws);                       // launch 1
    tG<<<32, 256>>>(x, Wt, bt);                     // launch 2
    gemmA_mma<<<dim3(8, 32), 512, SM_TOTAL>>>(x, bf, bs, sharp);  // launch 3 (ncu slot)
    sinkhorn<<<32, 1024>>>();
    gemmC_mma<<<dim3(8, 32), 256, SMC_TOTAL>>>();
    finalK<<<32, 1024>>>(anchors, out);
}